// round 1
// baseline (speedup 1.0000x reference)
#include <cuda_runtime.h>

// ---------------------------------------------------------------------------
// PairInteractionGrid on GB300 (sm_103a) — fp32 CUDA-core baseline w/ f32x2.
//
// reference:
//   p  = price  @ W_p + b_p                  (B,T,N,D)
//   v  = liquid @ W_v + b_v                  (B,T,M,D)
//   pair = [p_n, v_m, p_n*v_m, |p_n - v_m|]  (4D per (n,m))
//   h  = silu(pair @ W1 + b1)
//   out = h @ W2 + b2                        (B,T,N*M,D)
//
// Factorization: W1 = [W1p; W1v; Wc; Wd] (each DxD).
//   A  = p @ W1p            (per n, precomputed)
//   Bv = v @ W1v + b1       (per m, precomputed)
//   h_pre(n,m) = A_n + Bv_m + (p_n*v_m)@Wc + |p_n - v_m|@Wd
// ---------------------------------------------------------------------------

typedef unsigned long long ull;
#define DI __device__ __forceinline__

DI ull pack2(float lo, float hi) {
    ull r; asm("mov.b64 %0, {%1, %2};" : "=l"(r) : "f"(lo), "f"(hi)); return r;
}
DI void unpack2(ull v, float& lo, float& hi) {
    asm("mov.b64 {%0, %1}, %2;" : "=f"(lo), "=f"(hi) : "l"(v));
}
DI ull fma2(ull a, ull b, ull c) {
    ull d; asm("fma.rn.f32x2 %0, %1, %2, %3;" : "=l"(d) : "l"(a), "l"(b), "l"(c)); return d;
}
DI ull add2(ull a, ull b) {
    ull d; asm("add.rn.f32x2 %0, %1, %2;" : "=l"(d) : "l"(a), "l"(b)); return d;
}
DI ull mul2(ull a, ull b) {
    ull d; asm("mul.rn.f32x2 %0, %1, %2;" : "=l"(d) : "l"(a), "l"(b)); return d;
}
DI float silu_f(float x) { return __fdividef(x, 1.0f + __expf(-x)); }

// Problem dims
// B=4 T=64 N=32 M=32 D=128 ; BT=256 ; ROWS=8192 ; pairs=262144
// Scratch (static device arrays — no allocation)
__device__ float g_p  [8192 * 128];     // p[row][d]      row = bt*32+n
__device__ float g_A  [8192 * 128];     // A[row][k]
__device__ float g_vT [256 * 128 * 32]; // vT[bt][d][m]
__device__ float g_BvT[256 * 128 * 32]; // BvT[bt][k][m]  (b1 folded in)

// ---------------------------------------------------------------------------
// Kernel 1: precompute p, v, A, Bv.  grid (64, 2) x 256 threads.
//   blockIdx.y == 0 : price path  -> g_p, g_A      (row-major)
//   blockIdx.y == 1 : liquid path -> g_vT, g_BvT   (transposed per bt)
// Each block: 128 rows. smem: Win(64K) + W1x(64K) + X/Y tile 128x132 (67.5K)
// ---------------------------------------------------------------------------
__global__ void __launch_bounds__(256, 1) k_pre(
    const float* __restrict__ price, const float* __restrict__ liquid,
    const float* __restrict__ W_p, const float* __restrict__ b_p,
    const float* __restrict__ W_v, const float* __restrict__ b_v,
    const float* __restrict__ W1,  const float* __restrict__ b1)
{
    extern __shared__ float sm[];
    float* sW  = sm;           // [128][128]
    float* sW1 = sm + 16384;   // [128][128]
    float* sX  = sm + 32768;   // [128][132] padded

    const int path = blockIdx.y;
    const int r0   = blockIdx.x * 128;
    const float* X   = path ? liquid : price;
    const float* Wi  = path ? W_v : W_p;
    const float* bi  = path ? b_v : b_p;
    const float* W1x = path ? (W1 + 128 * 128) : W1;

    const int tid = threadIdx.x;
    const int rg = tid >> 4;        // 0..15 : rows rg*8..rg*8+7
    const int kg = tid & 15;        // 0..15 : cols kg*8..kg*8+7
    const int k0 = kg * 8;

    for (int i = tid; i < 4096; i += 256) {
        ((float4*)sW)[i]  = ((const float4*)Wi)[i];
        ((float4*)sW1)[i] = ((const float4*)W1x)[i];
    }
    for (int i = tid; i < 4096; i += 256) {
        int r = i >> 5, c = (i & 31) * 4;
        *(float4*)(sX + r * 132 + c) = *(const float4*)(X + (size_t)(r0 + r) * 128 + c);
    }
    __syncthreads();

    // ---- GEMM1: Y = X @ Wi + bi ----
    ull acc[8][4];
    {
        float4 blo = *(const float4*)(bi + k0);
        float4 bhi = *(const float4*)(bi + k0 + 4);
        ull i0 = pack2(blo.x, blo.y), i1 = pack2(blo.z, blo.w);
        ull i2 = pack2(bhi.x, bhi.y), i3 = pack2(bhi.z, bhi.w);
#pragma unroll
        for (int rl = 0; rl < 8; rl++) { acc[rl][0]=i0; acc[rl][1]=i1; acc[rl][2]=i2; acc[rl][3]=i3; }
    }
#pragma unroll 4
    for (int d = 0; d < 128; d++) {
        ulonglong2 wa = *(const ulonglong2*)(sW + d * 128 + k0);
        ulonglong2 wb = *(const ulonglong2*)(sW + d * 128 + k0 + 4);
        ull w2[4] = {wa.x, wa.y, wb.x, wb.y};
#pragma unroll
        for (int rl = 0; rl < 8; rl++) {
            float xv = sX[(rg * 8 + rl) * 132 + d];
            ull x2 = pack2(xv, xv);
#pragma unroll
            for (int kk = 0; kk < 4; kk++)
                acc[rl][kk] = fma2(x2, w2[kk], acc[rl][kk]);
        }
    }
    __syncthreads();

    // write Y into sX (reuse) + global
#pragma unroll
    for (int rl = 0; rl < 8; rl++) {
        float y[8];
#pragma unroll
        for (int kk = 0; kk < 4; kk++) unpack2(acc[rl][kk], y[2*kk], y[2*kk+1]);
        int r = rg * 8 + rl;
        *(float4*)(sX + r * 132 + k0)     = make_float4(y[0], y[1], y[2], y[3]);
        *(float4*)(sX + r * 132 + k0 + 4) = make_float4(y[4], y[5], y[6], y[7]);
        int row = r0 + r;
        if (path == 0) {
            *(float4*)(g_p + (size_t)row * 128 + k0)     = make_float4(y[0], y[1], y[2], y[3]);
            *(float4*)(g_p + (size_t)row * 128 + k0 + 4) = make_float4(y[4], y[5], y[6], y[7]);
        } else {
            int bt = row >> 5, m = row & 31;
            float* dst = g_vT + bt * 4096 + m;
#pragma unroll
            for (int kl = 0; kl < 8; kl++) dst[(k0 + kl) * 32] = y[kl];
        }
    }
    __syncthreads();

    // ---- GEMM2: Z = Y @ W1x  (+ b1 on liquid path) ----
    if (path == 0) {
#pragma unroll
        for (int rl = 0; rl < 8; rl++)
#pragma unroll
            for (int kk = 0; kk < 4; kk++) acc[rl][kk] = 0ULL;
    } else {
        float4 blo = *(const float4*)(b1 + k0);
        float4 bhi = *(const float4*)(b1 + k0 + 4);
        ull i0 = pack2(blo.x, blo.y), i1 = pack2(blo.z, blo.w);
        ull i2 = pack2(bhi.x, bhi.y), i3 = pack2(bhi.z, bhi.w);
#pragma unroll
        for (int rl = 0; rl < 8; rl++) { acc[rl][0]=i0; acc[rl][1]=i1; acc[rl][2]=i2; acc[rl][3]=i3; }
    }
#pragma unroll 4
    for (int d = 0; d < 128; d++) {
        ulonglong2 wa = *(const ulonglong2*)(sW1 + d * 128 + k0);
        ulonglong2 wb = *(const ulonglong2*)(sW1 + d * 128 + k0 + 4);
        ull w2[4] = {wa.x, wa.y, wb.x, wb.y};
#pragma unroll
        for (int rl = 0; rl < 8; rl++) {
            float xv = sX[(rg * 8 + rl) * 132 + d];
            ull x2 = pack2(xv, xv);
#pragma unroll
            for (int kk = 0; kk < 4; kk++)
                acc[rl][kk] = fma2(x2, w2[kk], acc[rl][kk]);
        }
    }
#pragma unroll
    for (int rl = 0; rl < 8; rl++) {
        float y[8];
#pragma unroll
        for (int kk = 0; kk < 4; kk++) unpack2(acc[rl][kk], y[2*kk], y[2*kk+1]);
        int row = r0 + rg * 8 + rl;
        if (path == 0) {
            *(float4*)(g_A + (size_t)row * 128 + k0)     = make_float4(y[0], y[1], y[2], y[3]);
            *(float4*)(g_A + (size_t)row * 128 + k0 + 4) = make_float4(y[4], y[5], y[6], y[7]);
        } else {
            int bt = row >> 5, m = row & 31;
            float* dst = g_BvT + bt * 4096 + m;
#pragma unroll
            for (int kl = 0; kl < 8; kl++) dst[(k0 + kl) * 32] = y[kl];
        }
    }
}

// ---------------------------------------------------------------------------
// Kernel 2: fused pair-interaction + MLP.  grid 2048 x 256 threads.
// Block = (bt, tile of 4 n's) -> 128 pairs x 128 outputs.
// Thread tile: 8 pairs (one n, 8 consecutive m) x 8 k, acc packed over m-pairs.
// Phase 1: h_pre = A + Bv + prod@Wc + abs@Wd, silu -> H in smem (xor-swizzled)
// Phase 2: out = H @ W2 + b2
// ---------------------------------------------------------------------------
__global__ void __launch_bounds__(256, 1) k_pair(
    const float* __restrict__ W1, const float* __restrict__ W2,
    const float* __restrict__ b2, float* __restrict__ out)
{
    extern __shared__ float sm[];
    float* sWc = sm;           // [128][128] prod weights ; phase2: W2
    float* sWd = sm + 16384;   // [128][128] abs weights  ; phase2: H (swizzled)
    float* sVT = sm + 32768;   // [128][32]
    float* sBT = sm + 36864;   // [128][32]
    float* sP  = sm + 40960;   // [4][128]
    float* sA  = sm + 41472;   // [4][128]

    const int tid  = threadIdx.x;
    const int bt   = blockIdx.x >> 3;
    const int tile = blockIdx.x & 7;
    const int rg = tid >> 4, kg = tid & 15;
    const int ln = rg >> 2;            // local n (0..3)
    const int m0 = (rg & 3) * 8;       // first m of this thread
    const int k0 = kg * 8;

    for (int i = tid; i < 4096; i += 256) {
        ((float4*)sWc)[i] = ((const float4*)(W1 + 256 * 128))[i];
        ((float4*)sWd)[i] = ((const float4*)(W1 + 384 * 128))[i];
    }
    for (int i = tid; i < 1024; i += 256) {
        ((float4*)sVT)[i] = ((const float4*)(g_vT  + (size_t)bt * 4096))[i];
        ((float4*)sBT)[i] = ((const float4*)(g_BvT + (size_t)bt * 4096))[i];
    }
    {
        const float* psrc = g_p + (size_t)(bt * 32 + tile * 4) * 128;
        const float* asrc = g_A + (size_t)(bt * 32 + tile * 4) * 128;
        for (int i = tid; i < 128; i += 256) {
            ((float4*)sP)[i] = ((const float4*)psrc)[i];
            ((float4*)sA)[i] = ((const float4*)asrc)[i];
        }
    }
    __syncthreads();

    const ull SIGN2 = 0x8000000080000000ULL;
    const ull ABS2  = 0x7FFFFFFF7FFFFFFFULL;

    ull acc[8][4];
#pragma unroll
    for (int kl = 0; kl < 8; kl++)
#pragma unroll
        for (int jj = 0; jj < 4; jj++) acc[kl][jj] = 0ULL;

    // ---- layer 1 main loop over d ----
#pragma unroll 4
    for (int d = 0; d < 128; d++) {
        float pv = sP[ln * 128 + d];
        ull p2 = pack2(pv, pv);
        ulonglong2 va = *(const ulonglong2*)(sVT + d * 32 + m0);
        ulonglong2 vb = *(const ulonglong2*)(sVT + d * 32 + m0 + 4);
        ull v2[4] = {va.x, va.y, vb.x, vb.y};
        ull t2[4], a2[4];
#pragma unroll
        for (int jj = 0; jj < 4; jj++) {
            t2[jj] = mul2(p2, v2[jj]);                      // p*v
            a2[jj] = add2(p2, v2[jj] ^ SIGN2) & ABS2;       // |p - v|
        }
        float4 wcl = *(const float4*)(sWc + d * 128 + k0);
        float4 wch = *(const float4*)(sWc + d * 128 + k0 + 4);
        float4 wdl = *(const float4*)(sWd + d * 128 + k0);
        float4 wdh = *(const float4*)(sWd + d * 128 + k0 + 4);
        float wc[8] = {wcl.x, wcl.y, wcl.z, wcl.w, wch.x, wch.y, wch.z, wch.w};
        float wd[8] = {wdl.x, wdl.y, wdl.z, wdl.w, wdh.x, wdh.y, wdh.z, wdh.w};
#pragma unroll
        for (int kl = 0; kl < 8; kl++) {
            ull wc2 = pack2(wc[kl], wc[kl]);
            ull wd2 = pack2(wd[kl], wd[kl]);
#pragma unroll
            for (int jj = 0; jj < 4; jj++) {
                acc[kl][jj] = fma2(t2[jj], wc2, acc[kl][jj]);
                acc[kl][jj] = fma2(a2[jj], wd2, acc[kl][jj]);
            }
        }
    }
    __syncthreads();   // everyone done reading sWc / sWd

    // ---- epilogue 1: + A + Bv, silu, store H (xor-swizzled) ----
    float* sH  = sWd;
    float* sW2 = sWc;
#pragma unroll
    for (int kl = 0; kl < 8; kl++) {
        int k = k0 + kl;
        float av = sA[ln * 128 + k];
        ull av2 = pack2(av, av);
        ulonglong2 ba = *(const ulonglong2*)(sBT + k * 32 + m0);
        ulonglong2 bb = *(const ulonglong2*)(sBT + k * 32 + m0 + 4);
        ull bv2[4] = {ba.x, ba.y, bb.x, bb.y};
        float h[8];
#pragma unroll
        for (int jj = 0; jj < 4; jj++) {
            ull s = add2(add2(acc[kl][jj], av2), bv2[jj]);
            float x0, x1;
            unpack2(s, x0, x1);
            h[2*jj]   = silu_f(x0);
            h[2*jj+1] = silu_f(x1);
        }
        int col = ((rg ^ k) & 15) * 8;   // bank-conflict swizzle
        *(float4*)(sH + k * 128 + col)     = make_float4(h[0], h[1], h[2], h[3]);
        *(float4*)(sH + k * 128 + col + 4) = make_float4(h[4], h[5], h[6], h[7]);
    }
    for (int i = tid; i < 4096; i += 256)
        ((float4*)sW2)[i] = ((const float4*)W2)[i];
    __syncthreads();

    // ---- layer 2: out = H @ W2 + b2 ----
    ull acc2[8][4];
#pragma unroll
    for (int el = 0; el < 8; el++)
#pragma unroll
        for (int jj = 0; jj < 4; jj++) acc2[el][jj] = 0ULL;

#pragma unroll 2
    for (int k = 0; k < 128; k++) {
        int col = ((rg ^ k) & 15) * 8;
        ulonglong2 ha = *(const ulonglong2*)(sH + k * 128 + col);
        ulonglong2 hb = *(const ulonglong2*)(sH + k * 128 + col + 4);
        ull h2[4] = {ha.x, ha.y, hb.x, hb.y};
        float4 wl = *(const float4*)(sW2 + k * 128 + k0);
        float4 wh = *(const float4*)(sW2 + k * 128 + k0 + 4);
        float w[8] = {wl.x, wl.y, wl.z, wl.w, wh.x, wh.y, wh.z, wh.w};
#pragma unroll
        for (int el = 0; el < 8; el++) {
            ull w2b = pack2(w[el], w[el]);
#pragma unroll
            for (int jj = 0; jj < 4; jj++)
                acc2[el][jj] = fma2(h2[jj], w2b, acc2[el][jj]);
        }
    }

    // ---- epilogue 2: + b2, write out ----
    float bb2[8];
    {
        float4 bl = *(const float4*)(b2 + k0);
        float4 bh = *(const float4*)(b2 + k0 + 4);
        bb2[0]=bl.x; bb2[1]=bl.y; bb2[2]=bl.z; bb2[3]=bl.w;
        bb2[4]=bh.x; bb2[5]=bh.y; bb2[6]=bh.z; bb2[7]=bh.w;
    }
    float* obase = out + ((size_t)blockIdx.x * 128 + rg * 8) * 128 + k0;
#pragma unroll
    for (int jj = 0; jj < 4; jj++) {
        float olo[8], ohi[8];
#pragma unroll
        for (int el = 0; el < 8; el++) {
            float lo, hi;
            unpack2(acc2[el][jj], lo, hi);
            olo[el] = lo + bb2[el];
            ohi[el] = hi + bb2[el];
        }
        *(float4*)(obase + (size_t)(2*jj) * 128)       = make_float4(olo[0], olo[1], olo[2], olo[3]);
        *(float4*)(obase + (size_t)(2*jj) * 128 + 4)   = make_float4(olo[4], olo[5], olo[6], olo[7]);
        *(float4*)(obase + (size_t)(2*jj+1) * 128)     = make_float4(ohi[0], ohi[1], ohi[2], ohi[3]);
        *(float4*)(obase + (size_t)(2*jj+1) * 128 + 4) = make_float4(ohi[4], ohi[5], ohi[6], ohi[7]);
    }
}

// ---------------------------------------------------------------------------
extern "C" void kernel_launch(void* const* d_in, const int* in_sizes, int n_in,
                              void* d_out, int out_size)
{
    const float* price  = (const float*)d_in[0];
    const float* liquid = (const float*)d_in[1];
    const float* W_p = (const float*)d_in[2];
    const float* b_p = (const float*)d_in[3];
    const float* W_v = (const float*)d_in[4];
    const float* b_v = (const float*)d_in[5];
    const float* W1  = (const float*)d_in[6];
    const float* b1  = (const float*)d_in[7];
    const float* W2  = (const float*)d_in[8];
    const float* b2  = (const float*)d_in[9];
    float* out = (float*)d_out;

    const size_t sm1 = (size_t)(16384 + 16384 + 128 * 132) * sizeof(float);  // 198656
    const size_t sm2 = (size_t)(16384 + 16384 + 4096 + 4096 + 512 + 512) * sizeof(float); // 167936
    cudaFuncSetAttribute(k_pre,  cudaFuncAttributeMaxDynamicSharedMemorySize, (int)sm1);
    cudaFuncSetAttribute(k_pair, cudaFuncAttributeMaxDynamicSharedMemorySize, (int)sm2);

    k_pre<<<dim3(64, 2), 256, sm1>>>(price, liquid, W_p, b_p, W_v, b_v, W1, b1);
    k_pair<<<2048, 256, sm2>>>(W1, W2, b2, out);
}

// round 3
// speedup vs baseline: 2.0616x; 2.0616x over previous
#include <cuda_runtime.h>
#include <cuda_bf16.h>
#include <cstdint>

// ---------------------------------------------------------------------------
// PairInteractionGrid (sm_103a, compute_103-safe) — mma.sync bf16 3-pass split.
//
//   p  = price  @ W_p + b_p ; v = liquid @ W_v + b_v
//   W1 = [W1p; W1v; Wc; Wd]:
//     A  = p @ W1p ; Bv = v @ W1v + b1          (k_pre, fp32 f32x2)
//     z(n,m) = A_n + Bv_m + (p*v)@Wc + |p-v|@Wd (HMMA, 3x bf16 split)
//   out = silu(z) @ W2 + b2                      (HMMA, 3x bf16 split)
// ---------------------------------------------------------------------------

typedef unsigned long long ull;
typedef unsigned int u32;
#define DI __device__ __forceinline__

DI ull pack2(float lo, float hi) {
    ull r; asm("mov.b64 %0, {%1, %2};" : "=l"(r) : "f"(lo), "f"(hi)); return r;
}
DI void unpack2(ull v, float& lo, float& hi) {
    asm("mov.b64 {%0, %1}, %2;" : "=f"(lo), "=f"(hi) : "l"(v));
}
DI ull fma2(ull a, ull b, ull c) {
    ull d; asm("fma.rn.f32x2 %0, %1, %2, %3;" : "=l"(d) : "l"(a), "l"(b), "l"(c)); return d;
}
DI float silu_f(float x) { return __fdividef(x, 1.0f + __expf(-x)); }

// pack two floats to bf16x2 (f0 -> low half) + hi/lo split
DI u32 cvt2(float f0, float f1) {
    u32 r; asm("cvt.rn.bf16x2.f32 %0, %1, %2;" : "=r"(r) : "f"(f1), "f"(f0)); return r;
}
DI void split2(float f0, float f1, u32& h, u32& l) {
    h = cvt2(f0, f1);
    float h0 = __uint_as_float(h << 16);
    float h1 = __uint_as_float(h & 0xFFFF0000u);
    l = cvt2(f0 - h0, f1 - h1);
}

// m16n8k16 row.col bf16 MMA, fp32 accumulate
DI void hmma(float* c, const u32* a, u32 b0, u32 b1) {
    asm("mma.sync.aligned.m16n8k16.row.col.f32.bf16.bf16.f32 "
        "{%0,%1,%2,%3},{%4,%5,%6,%7},{%8,%9},{%0,%1,%2,%3};"
        : "+f"(c[0]), "+f"(c[1]), "+f"(c[2]), "+f"(c[3])
        : "r"(a[0]), "r"(a[1]), "r"(a[2]), "r"(a[3]), "r"(b0), "r"(b1));
}

// ------------------------- global scratch ----------------------------------
// B=4 T=64 N=32 M=32 D=128 ; BT=256 ; units=2048 (bt * 8 tiles of 4 n)
__device__ __align__(16) float g_p  [8192 * 128];     // p[row][d]
__device__ __align__(16) float g_A  [8192 * 128];     // A[row][k]
__device__ __align__(16) float g_vT [256 * 128 * 32]; // vT[bt][d][m]
__device__ __align__(16) float g_BvT[256 * 128 * 32]; // BvT[bt][k][m] (b1 folded)
// 6 weight images, each [n=128][kpair=64 (+4 pad)] u32 of packed bf16 pairs:
// 0 Wc_hi, 1 Wc_lo, 2 Wd_hi, 3 Wd_lo, 4 W2_hi, 5 W2_lo
#define IMG_STRIDE 68
#define IMG_U32    (128 * IMG_STRIDE)   // 8704
__device__ __align__(16) u32 g_Wimg[6 * IMG_U32];

// ---------------------------------------------------------------------------
// Kernel 1: fp32 precompute of p, v, A, Bv (unchanged, passed R1).
// ---------------------------------------------------------------------------
__global__ void __launch_bounds__(256, 1) k_pre(
    const float* __restrict__ price, const float* __restrict__ liquid,
    const float* __restrict__ W_p, const float* __restrict__ b_p,
    const float* __restrict__ W_v, const float* __restrict__ b_v,
    const float* __restrict__ W1,  const float* __restrict__ b1)
{
    extern __shared__ float sm[];
    float* sW  = sm;           // [128][128]
    float* sW1 = sm + 16384;   // [128][128]
    float* sX  = sm + 32768;   // [128][132] padded

    const int path = blockIdx.y;
    const int r0   = blockIdx.x * 128;
    const float* X   = path ? liquid : price;
    const float* Wi  = path ? W_v : W_p;
    const float* bi  = path ? b_v : b_p;
    const float* W1x = path ? (W1 + 128 * 128) : W1;

    const int tid = threadIdx.x;
    const int rg = tid >> 4;
    const int kg = tid & 15;
    const int k0 = kg * 8;

    for (int i = tid; i < 4096; i += 256) {
        ((float4*)sW)[i]  = ((const float4*)Wi)[i];
        ((float4*)sW1)[i] = ((const float4*)W1x)[i];
    }
    for (int i = tid; i < 4096; i += 256) {
        int r = i >> 5, c = (i & 31) * 4;
        *(float4*)(sX + r * 132 + c) = *(const float4*)(X + (size_t)(r0 + r) * 128 + c);
    }
    __syncthreads();

    ull acc[8][4];
    {
        float4 blo = *(const float4*)(bi + k0);
        float4 bhi = *(const float4*)(bi + k0 + 4);
        ull i0 = pack2(blo.x, blo.y), i1 = pack2(blo.z, blo.w);
        ull i2 = pack2(bhi.x, bhi.y), i3 = pack2(bhi.z, bhi.w);
#pragma unroll
        for (int rl = 0; rl < 8; rl++) { acc[rl][0]=i0; acc[rl][1]=i1; acc[rl][2]=i2; acc[rl][3]=i3; }
    }
#pragma unroll 4
    for (int d = 0; d < 128; d++) {
        ulonglong2 wa = *(const ulonglong2*)(sW + d * 128 + k0);
        ulonglong2 wb = *(const ulonglong2*)(sW + d * 128 + k0 + 4);
        ull w2[4] = {wa.x, wa.y, wb.x, wb.y};
#pragma unroll
        for (int rl = 0; rl < 8; rl++) {
            float xv = sX[(rg * 8 + rl) * 132 + d];
            ull x2 = pack2(xv, xv);
#pragma unroll
            for (int kk = 0; kk < 4; kk++)
                acc[rl][kk] = fma2(x2, w2[kk], acc[rl][kk]);
        }
    }
    __syncthreads();

#pragma unroll
    for (int rl = 0; rl < 8; rl++) {
        float y[8];
#pragma unroll
        for (int kk = 0; kk < 4; kk++) unpack2(acc[rl][kk], y[2*kk], y[2*kk+1]);
        int r = rg * 8 + rl;
        *(float4*)(sX + r * 132 + k0)     = make_float4(y[0], y[1], y[2], y[3]);
        *(float4*)(sX + r * 132 + k0 + 4) = make_float4(y[4], y[5], y[6], y[7]);
        int row = r0 + r;
        if (path == 0) {
            *(float4*)(g_p + (size_t)row * 128 + k0)     = make_float4(y[0], y[1], y[2], y[3]);
            *(float4*)(g_p + (size_t)row * 128 + k0 + 4) = make_float4(y[4], y[5], y[6], y[7]);
        } else {
            int bt = row >> 5, m = row & 31;
            float* dst = g_vT + bt * 4096 + m;
#pragma unroll
            for (int kl = 0; kl < 8; kl++) dst[(k0 + kl) * 32] = y[kl];
        }
    }
    __syncthreads();

    if (path == 0) {
#pragma unroll
        for (int rl = 0; rl < 8; rl++)
#pragma unroll
            for (int kk = 0; kk < 4; kk++) acc[rl][kk] = 0ULL;
    } else {
        float4 blo = *(const float4*)(b1 + k0);
        float4 bhi = *(const float4*)(b1 + k0 + 4);
        ull i0 = pack2(blo.x, blo.y), i1 = pack2(blo.z, blo.w);
        ull i2 = pack2(bhi.x, bhi.y), i3 = pack2(bhi.z, bhi.w);
#pragma unroll
        for (int rl = 0; rl < 8; rl++) { acc[rl][0]=i0; acc[rl][1]=i1; acc[rl][2]=i2; acc[rl][3]=i3; }
    }
#pragma unroll 4
    for (int d = 0; d < 128; d++) {
        ulonglong2 wa = *(const ulonglong2*)(sW1 + d * 128 + k0);
        ulonglong2 wb = *(const ulonglong2*)(sW1 + d * 128 + k0 + 4);
        ull w2[4] = {wa.x, wa.y, wb.x, wb.y};
#pragma unroll
        for (int rl = 0; rl < 8; rl++) {
            float xv = sX[(rg * 8 + rl) * 132 + d];
            ull x2 = pack2(xv, xv);
#pragma unroll
            for (int kk = 0; kk < 4; kk++)
                acc[rl][kk] = fma2(x2, w2[kk], acc[rl][kk]);
        }
    }
#pragma unroll
    for (int rl = 0; rl < 8; rl++) {
        float y[8];
#pragma unroll
        for (int kk = 0; kk < 4; kk++) unpack2(acc[rl][kk], y[2*kk], y[2*kk+1]);
        int row = r0 + rg * 8 + rl;
        if (path == 0) {
            *(float4*)(g_A + (size_t)row * 128 + k0)     = make_float4(y[0], y[1], y[2], y[3]);
            *(float4*)(g_A + (size_t)row * 128 + k0 + 4) = make_float4(y[4], y[5], y[6], y[7]);
        } else {
            int bt = row >> 5, m = row & 31;
            float* dst = g_BvT + bt * 4096 + m;
#pragma unroll
            for (int kl = 0; kl < 8; kl++) dst[(k0 + kl) * 32] = y[kl];
        }
    }
}

// ---------------------------------------------------------------------------
// Kernel 2: weight prep — hi/lo bf16 split into b-fragment pair images.
// image[n][kp] = {W[2kp][n] (low), W[2kp+1][n] (high)}  (u32, stride 68)
// grid 3 x 128 threads (block = matrix: Wc, Wd, W2; thread = n).
// ---------------------------------------------------------------------------
__global__ void __launch_bounds__(128) k_wprep(const float* __restrict__ W1,
                                               const float* __restrict__ W2)
{
    const int mat = blockIdx.x;  // 0 Wc, 1 Wd, 2 W2
    const float* src = (mat == 0) ? (W1 + 256 * 128) : (mat == 1) ? (W1 + 384 * 128) : W2;
    u32* imgH = g_Wimg + (2 * mat)     * IMG_U32;
    u32* imgL = g_Wimg + (2 * mat + 1) * IMG_U32;
    const int n = threadIdx.x;
    for (int kp = 0; kp < 64; kp++) {
        float x0 = src[(2 * kp)     * 128 + n];
        float x1 = src[(2 * kp + 1) * 128 + n];
        u32 h, l;
        split2(x0, x1, h, l);
        imgH[n * IMG_STRIDE + kp] = h;
        imgL[n * IMG_STRIDE + kp] = l;
    }
}

// ---------------------------------------------------------------------------
// Kernel 3: persistent HMMA pair kernel. grid 148 x 256 threads.
// Unit u = (bt, tile of 4 n): 128 pair-rows x 128 outputs, K=128.
// Warp w: rows ln=w>>1 (32 m's), cols (w&1)*64 .. +64.
// smem slots (u32[4][8704]): phase1 = Wc_h, Wc_l, Wd_h, Wd_l
//                            phase2 = W2_h, W2_l, H_h,  H_l
// ---------------------------------------------------------------------------
__global__ void __launch_bounds__(256, 1) k_pair_mma(const float* __restrict__ b2,
                                                     float* __restrict__ out)
{
    extern __shared__ __align__(16) char smem[];
    u32*   sWt = (u32*)smem;                       // 4 * 8704 u32 = 139264 B
    float* sVT = (float*)(smem + 139264);          // [128][36] v[d][m]
    float* sBv = (float*)(smem + 157696);          // [128][36] Bv[k][m]
    float* sP  = (float*)(smem + 176128);          // [4][128]
    float* sA  = (float*)(smem + 178176);          // [4][128]
    float* sB2 = (float*)(smem + 180224);          // [128]

    const int tid  = threadIdx.x;
    const int w    = tid >> 5;
    const int lane = tid & 31;
    const int g    = lane >> 2;      // 0..7
    const int j    = lane & 3;       // 0..3
    const int ln   = w >> 1;         // local n 0..3 (warp's 32 rows = its m's)
    const int nb   = (w & 1) * 64;   // output-col base

    for (int i = tid; i < 128; i += 256) sB2[i] = b2[i];

    for (int u = blockIdx.x; u < 2048; u += gridDim.x) {
        const int bt = u >> 3, tile = u & 7;
        __syncthreads();   // previous unit fully done with smem

        // ---- stage: Wc/Wd images + vT + BvT + p + A ----
        {
            const uint4* wsrc = (const uint4*)g_Wimg;
            uint4* wdst = (uint4*)sWt;
            for (int i = tid; i < IMG_U32; i += 256) wdst[i] = wsrc[i];  // 4 imgs
            const float4* vsrc = (const float4*)(g_vT  + (size_t)bt * 4096);
            const float4* bsrc = (const float4*)(g_BvT + (size_t)bt * 4096);
            for (int i = tid; i < 1024; i += 256) {
                int d = i >> 3, mg = (i & 7) * 4;
                *(float4*)(sVT + d * 36 + mg) = vsrc[i];
                *(float4*)(sBv + d * 36 + mg) = bsrc[i];
            }
            if (tid < 128) {
                ((float4*)sP)[tid] = ((const float4*)(g_p + (size_t)(bt * 32 + tile * 4) * 128))[tid];
                ((float4*)sA)[tid] = ((const float4*)(g_A + (size_t)(bt * 32 + tile * 4) * 128))[tid];
            }
        }
        __syncthreads();

        // ---- layer 1: acc = (p*v)@Wc + |p-v|@Wd  (3-pass split) ----
        float acc[8][2][4];
#pragma unroll
        for (int nt = 0; nt < 8; nt++)
#pragma unroll
            for (int T = 0; T < 2; T++)
#pragma unroll
                for (int q = 0; q < 4; q++) acc[nt][T][q] = 0.0f;

#pragma unroll
        for (int s = 0; s < 8; s++) {
            const int c = 16 * s + 2 * j;
            float2 pA = *(const float2*)(sP + ln * 128 + c);
            float2 pB = *(const float2*)(sP + ln * 128 + c + 8);
            u32 Ph[2][4], Pl[2][4], Qh[2][4], Ql[2][4];
#pragma unroll
            for (int i = 0; i < 4; i++) {
                int m = g + 8 * i;
                float v0 = sVT[c * 36 + m],       v1 = sVT[(c + 1) * 36 + m];
                float v2 = sVT[(c + 8) * 36 + m], v3 = sVT[(c + 9) * 36 + m];
                int T = i >> 1, r = i & 1;
                split2(pA.x * v0, pA.y * v1, Ph[T][r],     Pl[T][r]);
                split2(pB.x * v2, pB.y * v3, Ph[T][r + 2], Pl[T][r + 2]);
                split2(fabsf(pA.x - v0), fabsf(pA.y - v1), Qh[T][r],     Ql[T][r]);
                split2(fabsf(pB.x - v2), fabsf(pB.y - v3), Qh[T][r + 2], Ql[T][r + 2]);
            }
#pragma unroll
            for (int nt = 0; nt < 8; nt++) {
                int bi = (nb + nt * 8 + g) * IMG_STRIDE + 8 * s + j;
                u32 ch0 = sWt[bi],                ch1 = sWt[bi + 4];
                u32 cl0 = sWt[IMG_U32 + bi],      cl1 = sWt[IMG_U32 + bi + 4];
                u32 dh0 = sWt[2 * IMG_U32 + bi],  dh1 = sWt[2 * IMG_U32 + bi + 4];
                u32 dl0 = sWt[3 * IMG_U32 + bi],  dl1 = sWt[3 * IMG_U32 + bi + 4];
#pragma unroll
                for (int T = 0; T < 2; T++) {
                    hmma(acc[nt][T], Ph[T], ch0, ch1);
                    hmma(acc[nt][T], Pl[T], ch0, ch1);
                    hmma(acc[nt][T], Ph[T], cl0, cl1);
                    hmma(acc[nt][T], Qh[T], dh0, dh1);
                    hmma(acc[nt][T], Ql[T], dh0, dh1);
                    hmma(acc[nt][T], Qh[T], dl0, dl1);
                }
            }
        }
        __syncthreads();   // done reading Wc/Wd slots

        // ---- load W2 into slots 0,1 ; epilogue 1 -> H in slots 2,3 ----
        {
            const uint4* wsrc = (const uint4*)(g_Wimg + 4 * IMG_U32);
            uint4* wdst = (uint4*)sWt;
            for (int i = tid; i < IMG_U32 / 2; i += 256) wdst[i] = wsrc[i];  // 2 imgs
        }
        u32* sHh = sWt + 2 * IMG_U32;
        u32* sHl = sWt + 3 * IMG_U32;
#pragma unroll
        for (int nt = 0; nt < 8; nt++)
#pragma unroll
            for (int T = 0; T < 2; T++) {
                int col = nb + nt * 8 + 2 * j;
                float a0 = sA[ln * 128 + col], a1 = sA[ln * 128 + col + 1];
#pragma unroll
                for (int hr = 0; hr < 2; hr++) {
                    int m = g + 16 * T + 8 * hr;
                    float z0 = acc[nt][T][2 * hr]     + a0 + sBv[col * 36 + m];
                    float z1 = acc[nt][T][2 * hr + 1] + a1 + sBv[(col + 1) * 36 + m];
                    u32 hh, hl;
                    split2(silu_f(z0), silu_f(z1), hh, hl);
                    int hi_ = (ln * 32 + m) * IMG_STRIDE + (col >> 1);
                    sHh[hi_] = hh;
                    sHl[hi_] = hl;
                }
            }
        __syncthreads();

        // ---- layer 2: out = H @ W2 (3-pass split) ----
        float ac2[8][2][4];
#pragma unroll
        for (int nt = 0; nt < 8; nt++)
#pragma unroll
            for (int T = 0; T < 2; T++)
#pragma unroll
                for (int q = 0; q < 4; q++) ac2[nt][T][q] = 0.0f;

#pragma unroll
        for (int s = 0; s < 8; s++) {
            u32 Ah[2][4], Al[2][4];
#pragma unroll
            for (int T = 0; T < 2; T++) {
                int r0 = (ln * 32 + g + 16 * T) * IMG_STRIDE + 8 * s + j;
                Ah[T][0] = sHh[r0];
                Ah[T][1] = sHh[r0 + 8 * IMG_STRIDE];
                Ah[T][2] = sHh[r0 + 4];
                Ah[T][3] = sHh[r0 + 8 * IMG_STRIDE + 4];
                Al[T][0] = sHl[r0];
                Al[T][1] = sHl[r0 + 8 * IMG_STRIDE];
                Al[T][2] = sHl[r0 + 4];
                Al[T][3] = sHl[r0 + 8 * IMG_STRIDE + 4];
            }
#pragma unroll
            for (int nt = 0; nt < 8; nt++) {
                int bi = (nb + nt * 8 + g) * IMG_STRIDE + 8 * s + j;
                u32 wh0 = sWt[bi],           wh1 = sWt[bi + 4];
                u32 wl0 = sWt[IMG_U32 + bi], wl1 = sWt[IMG_U32 + bi + 4];
#pragma unroll
                for (int T = 0; T < 2; T++) {
                    hmma(ac2[nt][T], Ah[T], wh0, wh1);
                    hmma(ac2[nt][T], Al[T], wh0, wh1);
                    hmma(ac2[nt][T], Ah[T], wl0, wl1);
                }
            }
        }

        // ---- epilogue 2: + b2, store ----
        float* ob = out + (size_t)u * 128 * 128;
#pragma unroll
        for (int nt = 0; nt < 8; nt++)
#pragma unroll
            for (int T = 0; T < 2; T++) {
                int col = nb + nt * 8 + 2 * j;
                float bb0 = sB2[col], bb1 = sB2[col + 1];
#pragma unroll
                for (int hr = 0; hr < 2; hr++) {
                    int m = g + 16 * T + 8 * hr;
                    float2 o;
                    o.x = ac2[nt][T][2 * hr]     + bb0;
                    o.y = ac2[nt][T][2 * hr + 1] + bb1;
                    *(float2*)(ob + (size_t)(ln * 32 + m) * 128 + col) = o;
                }
            }
    }
}

// ---------------------------------------------------------------------------
extern "C" void kernel_launch(void* const* d_in, const int* in_sizes, int n_in,
                              void* d_out, int out_size)
{
    const float* price  = (const float*)d_in[0];
    const float* liquid = (const float*)d_in[1];
    const float* W_p = (const float*)d_in[2];
    const float* b_p = (const float*)d_in[3];
    const float* W_v = (const float*)d_in[4];
    const float* b_v = (const float*)d_in[5];
    const float* W1  = (const float*)d_in[6];
    const float* b1  = (const float*)d_in[7];
    const float* W2  = (const float*)d_in[8];
    const float* b2  = (const float*)d_in[9];
    float* out = (float*)d_out;

    const size_t sm1 = (size_t)(16384 + 16384 + 128 * 132) * sizeof(float);  // 198656
    const size_t sm2 = 139264 + 18432 + 18432 + 2048 + 2048 + 512;           // 180736
    cudaFuncSetAttribute(k_pre,      cudaFuncAttributeMaxDynamicSharedMemorySize, (int)sm1);
    cudaFuncSetAttribute(k_pair_mma, cudaFuncAttributeMaxDynamicSharedMemorySize, (int)sm2);

    k_pre<<<dim3(64, 2), 256, sm1>>>(price, liquid, W_p, b_p, W_v, b_v, W1, b1);
    k_wprep<<<3, 128>>>(W1, W2);
    k_pair_mma<<<148, 256, sm2>>>(b2, out);
}

// round 4
// speedup vs baseline: 2.0909x; 1.0142x over previous
#include <cuda_runtime.h>
#include <cuda_bf16.h>
#include <cstdint>

// ---------------------------------------------------------------------------
// PairInteractionGrid (sm_103a, compute_103-safe) — mma.sync bf16 3-pass split.
//
//   p  = price  @ W_p + b_p ; v = liquid @ W_v + b_v
//   W1 = [W1p; W1v; Wc; Wd]:
//     A  = p @ W1p ; Bv = v @ W1v + b1          (k_pre, fp32 f32x2)
//     z(n,m) = A_n + Bv_m + (p*v)@Wc + |p-v|@Wd (HMMA, 3x bf16 split)
//   out = silu(z) @ W2 + b2                      (HMMA, 3x bf16 split)
// ---------------------------------------------------------------------------

typedef unsigned long long ull;
typedef unsigned int u32;
#define DI __device__ __forceinline__

DI ull pack2(float lo, float hi) {
    ull r; asm("mov.b64 %0, {%1, %2};" : "=l"(r) : "f"(lo), "f"(hi)); return r;
}
DI void unpack2(ull v, float& lo, float& hi) {
    asm("mov.b64 {%0, %1}, %2;" : "=f"(lo), "=f"(hi) : "l"(v));
}
DI ull fma2(ull a, ull b, ull c) {
    ull d; asm("fma.rn.f32x2 %0, %1, %2, %3;" : "=l"(d) : "l"(a), "l"(b), "l"(c)); return d;
}
DI float silu_f(float x) { return __fdividef(x, 1.0f + __expf(-x)); }

// pack two floats to bf16x2 (f0 -> low half) + hi/lo split
DI u32 cvt2(float f0, float f1) {
    u32 r; asm("cvt.rn.bf16x2.f32 %0, %1, %2;" : "=r"(r) : "f"(f1), "f"(f0)); return r;
}
DI void split2(float f0, float f1, u32& h, u32& l) {
    h = cvt2(f0, f1);
    float h0 = __uint_as_float(h << 16);
    float h1 = __uint_as_float(h & 0xFFFF0000u);
    l = cvt2(f0 - h0, f1 - h1);
}

// m16n8k16 row.col bf16 MMA, fp32 accumulate
DI void hmma(float* c, const u32* a, u32 b0, u32 b1) {
    asm("mma.sync.aligned.m16n8k16.row.col.f32.bf16.bf16.f32 "
        "{%0,%1,%2,%3},{%4,%5,%6,%7},{%8,%9},{%0,%1,%2,%3};"
        : "+f"(c[0]), "+f"(c[1]), "+f"(c[2]), "+f"(c[3])
        : "r"(a[0]), "r"(a[1]), "r"(a[2]), "r"(a[3]), "r"(b0), "r"(b1));
}

// ------------------------- global scratch ----------------------------------
// B=4 T=64 N=32 M=32 D=128 ; BT=256 ; units=2048 (bt * 8 tiles of 4 n)
__device__ __align__(16) float g_p  [8192 * 128];     // p[row][d]
__device__ __align__(16) float g_A  [8192 * 128];     // A[row][k]
__device__ __align__(16) float g_vT [256 * 128 * 32]; // vT[bt][d][m]
__device__ __align__(16) float g_BvT[256 * 128 * 32]; // BvT[bt][k][m] (b1 folded)
// 6 weight images, each [n=128][kpair=64 (+4 pad)] u32 of packed bf16 pairs:
// 0 Wc_hi, 1 Wc_lo, 2 Wd_hi, 3 Wd_lo, 4 W2_hi, 5 W2_lo
#define IMG_STRIDE 68
#define IMG_U32    (128 * IMG_STRIDE)   // 8704
__device__ __align__(16) u32 g_Wimg[6 * IMG_U32];

// ---------------------------------------------------------------------------
// Kernel 1: fp32 precompute of p, v, A, Bv (unchanged, passed R1).
// ---------------------------------------------------------------------------
__global__ void __launch_bounds__(256, 1) k_pre(
    const float* __restrict__ price, const float* __restrict__ liquid,
    const float* __restrict__ W_p, const float* __restrict__ b_p,
    const float* __restrict__ W_v, const float* __restrict__ b_v,
    const float* __restrict__ W1,  const float* __restrict__ b1)
{
    extern __shared__ float sm[];
    float* sW  = sm;           // [128][128]
    float* sW1 = sm + 16384;   // [128][128]
    float* sX  = sm + 32768;   // [128][132] padded

    const int path = blockIdx.y;
    const int r0   = blockIdx.x * 128;
    const float* X   = path ? liquid : price;
    const float* Wi  = path ? W_v : W_p;
    const float* bi  = path ? b_v : b_p;
    const float* W1x = path ? (W1 + 128 * 128) : W1;

    const int tid = threadIdx.x;
    const int rg = tid >> 4;
    const int kg = tid & 15;
    const int k0 = kg * 8;

    for (int i = tid; i < 4096; i += 256) {
        ((float4*)sW)[i]  = ((const float4*)Wi)[i];
        ((float4*)sW1)[i] = ((const float4*)W1x)[i];
    }
    for (int i = tid; i < 4096; i += 256) {
        int r = i >> 5, c = (i & 31) * 4;
        *(float4*)(sX + r * 132 + c) = *(const float4*)(X + (size_t)(r0 + r) * 128 + c);
    }
    __syncthreads();

    ull acc[8][4];
    {
        float4 blo = *(const float4*)(bi + k0);
        float4 bhi = *(const float4*)(bi + k0 + 4);
        ull i0 = pack2(blo.x, blo.y), i1 = pack2(blo.z, blo.w);
        ull i2 = pack2(bhi.x, bhi.y), i3 = pack2(bhi.z, bhi.w);
#pragma unroll
        for (int rl = 0; rl < 8; rl++) { acc[rl][0]=i0; acc[rl][1]=i1; acc[rl][2]=i2; acc[rl][3]=i3; }
    }
#pragma unroll 4
    for (int d = 0; d < 128; d++) {
        ulonglong2 wa = *(const ulonglong2*)(sW + d * 128 + k0);
        ulonglong2 wb = *(const ulonglong2*)(sW + d * 128 + k0 + 4);
        ull w2[4] = {wa.x, wa.y, wb.x, wb.y};
#pragma unroll
        for (int rl = 0; rl < 8; rl++) {
            float xv = sX[(rg * 8 + rl) * 132 + d];
            ull x2 = pack2(xv, xv);
#pragma unroll
            for (int kk = 0; kk < 4; kk++)
                acc[rl][kk] = fma2(x2, w2[kk], acc[rl][kk]);
        }
    }
    __syncthreads();

#pragma unroll
    for (int rl = 0; rl < 8; rl++) {
        float y[8];
#pragma unroll
        for (int kk = 0; kk < 4; kk++) unpack2(acc[rl][kk], y[2*kk], y[2*kk+1]);
        int r = rg * 8 + rl;
        *(float4*)(sX + r * 132 + k0)     = make_float4(y[0], y[1], y[2], y[3]);
        *(float4*)(sX + r * 132 + k0 + 4) = make_float4(y[4], y[5], y[6], y[7]);
        int row = r0 + r;
        if (path == 0) {
            *(float4*)(g_p + (size_t)row * 128 + k0)     = make_float4(y[0], y[1], y[2], y[3]);
            *(float4*)(g_p + (size_t)row * 128 + k0 + 4) = make_float4(y[4], y[5], y[6], y[7]);
        } else {
            int bt = row >> 5, m = row & 31;
            float* dst = g_vT + bt * 4096 + m;
#pragma unroll
            for (int kl = 0; kl < 8; kl++) dst[(k0 + kl) * 32] = y[kl];
        }
    }
    __syncthreads();

    if (path == 0) {
#pragma unroll
        for (int rl = 0; rl < 8; rl++)
#pragma unroll
            for (int kk = 0; kk < 4; kk++) acc[rl][kk] = 0ULL;
    } else {
        float4 blo = *(const float4*)(b1 + k0);
        float4 bhi = *(const float4*)(b1 + k0 + 4);
        ull i0 = pack2(blo.x, blo.y), i1 = pack2(blo.z, blo.w);
        ull i2 = pack2(bhi.x, bhi.y), i3 = pack2(bhi.z, bhi.w);
#pragma unroll
        for (int rl = 0; rl < 8; rl++) { acc[rl][0]=i0; acc[rl][1]=i1; acc[rl][2]=i2; acc[rl][3]=i3; }
    }
#pragma unroll 4
    for (int d = 0; d < 128; d++) {
        ulonglong2 wa = *(const ulonglong2*)(sW1 + d * 128 + k0);
        ulonglong2 wb = *(const ulonglong2*)(sW1 + d * 128 + k0 + 4);
        ull w2[4] = {wa.x, wa.y, wb.x, wb.y};
#pragma unroll
        for (int rl = 0; rl < 8; rl++) {
            float xv = sX[(rg * 8 + rl) * 132 + d];
            ull x2 = pack2(xv, xv);
#pragma unroll
            for (int kk = 0; kk < 4; kk++)
                acc[rl][kk] = fma2(x2, w2[kk], acc[rl][kk]);
        }
    }
#pragma unroll
    for (int rl = 0; rl < 8; rl++) {
        float y[8];
#pragma unroll
        for (int kk = 0; kk < 4; kk++) unpack2(acc[rl][kk], y[2*kk], y[2*kk+1]);
        int row = r0 + rg * 8 + rl;
        if (path == 0) {
            *(float4*)(g_A + (size_t)row * 128 + k0)     = make_float4(y[0], y[1], y[2], y[3]);
            *(float4*)(g_A + (size_t)row * 128 + k0 + 4) = make_float4(y[4], y[5], y[6], y[7]);
        } else {
            int bt = row >> 5, m = row & 31;
            float* dst = g_BvT + bt * 4096 + m;
#pragma unroll
            for (int kl = 0; kl < 8; kl++) dst[(k0 + kl) * 32] = y[kl];
        }
    }
}

// ---------------------------------------------------------------------------
// Kernel 2: weight prep — hi/lo bf16 split into b-fragment pair images.
// image[n][kp] = {W[2kp][n] (low), W[2kp+1][n] (high)}  (u32, stride 68)
// grid 3 x 128 threads (block = matrix: Wc, Wd, W2; thread = n).
// ---------------------------------------------------------------------------
__global__ void __launch_bounds__(128) k_wprep(const float* __restrict__ W1,
                                               const float* __restrict__ W2)
{
    const int mat = blockIdx.x;  // 0 Wc, 1 Wd, 2 W2
    const float* src = (mat == 0) ? (W1 + 256 * 128) : (mat == 1) ? (W1 + 384 * 128) : W2;
    u32* imgH = g_Wimg + (2 * mat)     * IMG_U32;
    u32* imgL = g_Wimg + (2 * mat + 1) * IMG_U32;
    const int n = threadIdx.x;
    for (int kp = 0; kp < 64; kp++) {
        float x0 = src[(2 * kp)     * 128 + n];
        float x1 = src[(2 * kp + 1) * 128 + n];
        u32 h, l;
        split2(x0, x1, h, l);
        imgH[n * IMG_STRIDE + kp] = h;
        imgL[n * IMG_STRIDE + kp] = l;
    }
}

// ---------------------------------------------------------------------------
// Kernel 3: persistent HMMA pair kernel. grid 148 x 256 threads.
// Unit u = (bt, tile of 4 n): 128 pair-rows x 128 outputs, K=128.
// Warp w: rows ln=w>>1 (32 m's), cols (w&1)*64 .. +64.
// smem slots (u32[4][8704]): phase1 = Wc_h, Wc_l, Wd_h, Wd_l
//                            phase2 = W2_h, W2_l, H_h,  H_l
// ---------------------------------------------------------------------------
__global__ void __launch_bounds__(256, 1) k_pair_mma(const float* __restrict__ b2,
                                                     float* __restrict__ out)
{
    extern __shared__ __align__(16) char smem[];
    u32*   sWt = (u32*)smem;                       // 4 * 8704 u32 = 139264 B
    float* sVT = (float*)(smem + 139264);          // [128][36] v[d][m]
    float* sBv = (float*)(smem + 157696);          // [128][36] Bv[k][m]
    float* sP  = (float*)(smem + 176128);          // [4][128]
    float* sA  = (float*)(smem + 178176);          // [4][128]
    float* sB2 = (float*)(smem + 180224);          // [128]

    const int tid  = threadIdx.x;
    const int w    = tid >> 5;
    const int lane = tid & 31;
    const int g    = lane >> 2;      // 0..7
    const int j    = lane & 3;       // 0..3
    const int ln   = w >> 1;         // local n 0..3 (warp's 32 rows = its m's)
    const int nb   = (w & 1) * 64;   // output-col base

    for (int i = tid; i < 128; i += 256) sB2[i] = b2[i];

    for (int u = blockIdx.x; u < 2048; u += gridDim.x) {
        const int bt = u >> 3, tile = u & 7;
        __syncthreads();   // previous unit fully done with smem

        // ---- stage: Wc/Wd images + vT + BvT + p + A ----
        {
            const uint4* wsrc = (const uint4*)g_Wimg;
            uint4* wdst = (uint4*)sWt;
            for (int i = tid; i < IMG_U32; i += 256) wdst[i] = wsrc[i];  // 4 imgs
            const float4* vsrc = (const float4*)(g_vT  + (size_t)bt * 4096);
            const float4* bsrc = (const float4*)(g_BvT + (size_t)bt * 4096);
            for (int i = tid; i < 1024; i += 256) {
                int d = i >> 3, mg = (i & 7) * 4;
                *(float4*)(sVT + d * 36 + mg) = vsrc[i];
                *(float4*)(sBv + d * 36 + mg) = bsrc[i];
            }
            if (tid < 128) {
                ((float4*)sP)[tid] = ((const float4*)(g_p + (size_t)(bt * 32 + tile * 4) * 128))[tid];
                ((float4*)sA)[tid] = ((const float4*)(g_A + (size_t)(bt * 32 + tile * 4) * 128))[tid];
            }
        }
        __syncthreads();

        // ---- layer 1: acc = (p*v)@Wc + |p-v|@Wd  (3-pass split) ----
        float acc[8][2][4];
#pragma unroll
        for (int nt = 0; nt < 8; nt++)
#pragma unroll
            for (int T = 0; T < 2; T++)
#pragma unroll
                for (int q = 0; q < 4; q++) acc[nt][T][q] = 0.0f;

#pragma unroll
        for (int s = 0; s < 8; s++) {
            const int c = 16 * s + 2 * j;
            float2 pA = *(const float2*)(sP + ln * 128 + c);
            float2 pB = *(const float2*)(sP + ln * 128 + c + 8);
            u32 Ph[2][4], Pl[2][4], Qh[2][4], Ql[2][4];
#pragma unroll
            for (int i = 0; i < 4; i++) {
                int m = g + 8 * i;
                float v0 = sVT[c * 36 + m],       v1 = sVT[(c + 1) * 36 + m];
                float v2 = sVT[(c + 8) * 36 + m], v3 = sVT[(c + 9) * 36 + m];
                int T = i >> 1, r = i & 1;
                split2(pA.x * v0, pA.y * v1, Ph[T][r],     Pl[T][r]);
                split2(pB.x * v2, pB.y * v3, Ph[T][r + 2], Pl[T][r + 2]);
                split2(fabsf(pA.x - v0), fabsf(pA.y - v1), Qh[T][r],     Ql[T][r]);
                split2(fabsf(pB.x - v2), fabsf(pB.y - v3), Qh[T][r + 2], Ql[T][r + 2]);
            }
#pragma unroll
            for (int nt = 0; nt < 8; nt++) {
                int bi = (nb + nt * 8 + g) * IMG_STRIDE + 8 * s + j;
                u32 ch0 = sWt[bi],                ch1 = sWt[bi + 4];
                u32 cl0 = sWt[IMG_U32 + bi],      cl1 = sWt[IMG_U32 + bi + 4];
                u32 dh0 = sWt[2 * IMG_U32 + bi],  dh1 = sWt[2 * IMG_U32 + bi + 4];
                u32 dl0 = sWt[3 * IMG_U32 + bi],  dl1 = sWt[3 * IMG_U32 + bi + 4];
#pragma unroll
                for (int T = 0; T < 2; T++) {
                    hmma(acc[nt][T], Ph[T], ch0, ch1);
                    hmma(acc[nt][T], Pl[T], ch0, ch1);
                    hmma(acc[nt][T], Ph[T], cl0, cl1);
                    hmma(acc[nt][T], Qh[T], dh0, dh1);
                    hmma(acc[nt][T], Ql[T], dh0, dh1);
                    hmma(acc[nt][T], Qh[T], dl0, dl1);
                }
            }
        }
        __syncthreads();   // done reading Wc/Wd slots

        // ---- load W2 into slots 0,1 ; epilogue 1 -> H in slots 2,3 ----
        {
            const uint4* wsrc = (const uint4*)(g_Wimg + 4 * IMG_U32);
            uint4* wdst = (uint4*)sWt;
            for (int i = tid; i < IMG_U32 / 2; i += 256) wdst[i] = wsrc[i];  // 2 imgs
        }
        u32* sHh = sWt + 2 * IMG_U32;
        u32* sHl = sWt + 3 * IMG_U32;
#pragma unroll
        for (int nt = 0; nt < 8; nt++)
#pragma unroll
            for (int T = 0; T < 2; T++) {
                int col = nb + nt * 8 + 2 * j;
                float a0 = sA[ln * 128 + col], a1 = sA[ln * 128 + col + 1];
#pragma unroll
                for (int hr = 0; hr < 2; hr++) {
                    int m = g + 16 * T + 8 * hr;
                    float z0 = acc[nt][T][2 * hr]     + a0 + sBv[col * 36 + m];
                    float z1 = acc[nt][T][2 * hr + 1] + a1 + sBv[(col + 1) * 36 + m];
                    u32 hh, hl;
                    split2(silu_f(z0), silu_f(z1), hh, hl);
                    int hi_ = (ln * 32 + m) * IMG_STRIDE + (col >> 1);
                    sHh[hi_] = hh;
                    sHl[hi_] = hl;
                }
            }
        __syncthreads();

        // ---- layer 2: out = H @ W2 (3-pass split) ----
        float ac2[8][2][4];
#pragma unroll
        for (int nt = 0; nt < 8; nt++)
#pragma unroll
            for (int T = 0; T < 2; T++)
#pragma unroll
                for (int q = 0; q < 4; q++) ac2[nt][T][q] = 0.0f;

#pragma unroll
        for (int s = 0; s < 8; s++) {
            u32 Ah[2][4], Al[2][4];
#pragma unroll
            for (int T = 0; T < 2; T++) {
                int r0 = (ln * 32 + g + 16 * T) * IMG_STRIDE + 8 * s + j;
                Ah[T][0] = sHh[r0];
                Ah[T][1] = sHh[r0 + 8 * IMG_STRIDE];
                Ah[T][2] = sHh[r0 + 4];
                Ah[T][3] = sHh[r0 + 8 * IMG_STRIDE + 4];
                Al[T][0] = sHl[r0];
                Al[T][1] = sHl[r0 + 8 * IMG_STRIDE];
                Al[T][2] = sHl[r0 + 4];
                Al[T][3] = sHl[r0 + 8 * IMG_STRIDE + 4];
            }
#pragma unroll
            for (int nt = 0; nt < 8; nt++) {
                int bi = (nb + nt * 8 + g) * IMG_STRIDE + 8 * s + j;
                u32 wh0 = sWt[bi],           wh1 = sWt[bi + 4];
                u32 wl0 = sWt[IMG_U32 + bi], wl1 = sWt[IMG_U32 + bi + 4];
#pragma unroll
                for (int T = 0; T < 2; T++) {
                    hmma(ac2[nt][T], Ah[T], wh0, wh1);
                    hmma(ac2[nt][T], Al[T], wh0, wh1);
                    hmma(ac2[nt][T], Ah[T], wl0, wl1);
                }
            }
        }

        // ---- epilogue 2: + b2, store ----
        float* ob = out + (size_t)u * 128 * 128;
#pragma unroll
        for (int nt = 0; nt < 8; nt++)
#pragma unroll
            for (int T = 0; T < 2; T++) {
                int col = nb + nt * 8 + 2 * j;
                float bb0 = sB2[col], bb1 = sB2[col + 1];
#pragma unroll
                for (int hr = 0; hr < 2; hr++) {
                    int m = g + 16 * T + 8 * hr;
                    float2 o;
                    o.x = ac2[nt][T][2 * hr]     + bb0;
                    o.y = ac2[nt][T][2 * hr + 1] + bb1;
                    *(float2*)(ob + (size_t)(ln * 32 + m) * 128 + col) = o;
                }
            }
    }
}

// ---------------------------------------------------------------------------
extern "C" void kernel_launch(void* const* d_in, const int* in_sizes, int n_in,
                              void* d_out, int out_size)
{
    const float* price  = (const float*)d_in[0];
    const float* liquid = (const float*)d_in[1];
    const float* W_p = (const float*)d_in[2];
    const float* b_p = (const float*)d_in[3];
    const float* W_v = (const float*)d_in[4];
    const float* b_v = (const float*)d_in[5];
    const float* W1  = (const float*)d_in[6];
    const float* b1  = (const float*)d_in[7];
    const float* W2  = (const float*)d_in[8];
    const float* b2  = (const float*)d_in[9];
    float* out = (float*)d_out;

    const size_t sm1 = (size_t)(16384 + 16384 + 128 * 132) * sizeof(float);  // 198656
    const size_t sm2 = 139264 + 18432 + 18432 + 2048 + 2048 + 512;           // 180736
    cudaFuncSetAttribute(k_pre,      cudaFuncAttributeMaxDynamicSharedMemorySize, (int)sm1);
    cudaFuncSetAttribute(k_pair_mma, cudaFuncAttributeMaxDynamicSharedMemorySize, (int)sm2);

    k_pre<<<dim3(64, 2), 256, sm1>>>(price, liquid, W_p, b_p, W_v, b_v, W1, b1);
    k_wprep<<<3, 128>>>(W1, W2);
    k_pair_mma<<<148, 256, sm2>>>(b2, out);
}

// round 5
// speedup vs baseline: 2.6525x; 1.2686x over previous
#include <cuda_runtime.h>
#include <cuda_bf16.h>
#include <cstdint>

// ---------------------------------------------------------------------------
// PairInteractionGrid (sm_103a) R4 — sync-free warp-independent HMMA design.
//   p  = price @ W_p + b_p ; v = liquid @ W_v + b_v         (k_pre, f32x2)
//   A  = p @ W1p ; Bv = v @ W1v + b1                         (k_pre)
//   z(n,m) = A_n + Bv_m + (p*v)@Wc + |p-v|@Wd                (k_pair, HMMA 3x)
//   out = silu(z) @ W2 + b2                                  (k_pair, HMMA 3x)
// Warp = 16 pair-rows x 128 cols; H stays in registers (C-frag == A-frag).
// ---------------------------------------------------------------------------

typedef unsigned long long ull;
typedef unsigned int u32;
#define DI __device__ __forceinline__

DI ull pack2(float lo, float hi) {
    ull r; asm("mov.b64 %0, {%1, %2};" : "=l"(r) : "f"(lo), "f"(hi)); return r;
}
DI void unpack2(ull v, float& lo, float& hi) {
    asm("mov.b64 {%0, %1}, %2;" : "=f"(lo), "=f"(hi) : "l"(v));
}
DI ull fma2(ull a, ull b, ull c) {
    ull d; asm("fma.rn.f32x2 %0, %1, %2, %3;" : "=l"(d) : "l"(a), "l"(b), "l"(c)); return d;
}
DI float silu_f(float x) { return __fdividef(x, 1.0f + __expf(-x)); }

DI u32 cvt2(float f0, float f1) {   // f0 -> low half bf16x2
    u32 r; asm("cvt.rn.bf16x2.f32 %0, %1, %2;" : "=r"(r) : "f"(f1), "f"(f0)); return r;
}
DI void split2(float f0, float f1, u32& h, u32& l) {
    h = cvt2(f0, f1);
    float h0 = __uint_as_float(h << 16);
    float h1 = __uint_as_float(h & 0xFFFF0000u);
    l = cvt2(f0 - h0, f1 - h1);
}
DI void hmma(float* c, const u32* a, u32 b0, u32 b1) {
    asm("mma.sync.aligned.m16n8k16.row.col.f32.bf16.bf16.f32 "
        "{%0,%1,%2,%3},{%4,%5,%6,%7},{%8,%9},{%0,%1,%2,%3};"
        : "+f"(c[0]), "+f"(c[1]), "+f"(c[2]), "+f"(c[3])
        : "r"(a[0]), "r"(a[1]), "r"(a[2]), "r"(a[3]), "r"(b0), "r"(b1));
}

// ------------------------- global scratch ----------------------------------
// B=4 T=64 N=32 M=32 D=128 ; BT=256 ; units=2048 (bt * 8 tiles of 4 n)
__device__ __align__(16) float g_p  [8192 * 128];     // p[row][d]
__device__ __align__(16) float g_A  [8192 * 128];     // A[row][k]
__device__ __align__(16) float g_vT [256 * 128 * 32]; // vT[bt][d][m]
__device__ __align__(16) float g_BvT[256 * 128 * 32]; // BvT[bt][k][m] (b1 folded)
// 6 images: 0 Wc_h, 1 Wc_l, 2 Wd_h, 3 Wd_l, 4 W2_h, 5 W2_l.
// img[im][n][4s+j] = uint2{ bf16x2(W[16s+2j][n],W[16s+2j+1][n]),
//                           bf16x2(W[16s+2j+8][n],W[16s+2j+9][n]) }
#define IMG_S2 36                 // uint2 stride per n (4 pad)
#define IMG_N  (128 * IMG_S2)     // 4608 uint2 per image (36,864 B)
__device__ __align__(16) uint2 g_img[6 * IMG_N];

// ---------------------------------------------------------------------------
// Kernel 1: fp32 precompute of p, v, A, Bv. 64-row blocks, 2 CTAs/SM.
// grid (128, 2) x 256 thr; smem = sW[128][128] + sX[64][132] = 99,328 B.
// ---------------------------------------------------------------------------
__global__ void __launch_bounds__(256, 2) k_pre(
    const float* __restrict__ price, const float* __restrict__ liquid,
    const float* __restrict__ W_p, const float* __restrict__ b_p,
    const float* __restrict__ W_v, const float* __restrict__ b_v,
    const float* __restrict__ W1,  const float* __restrict__ b1)
{
    extern __shared__ float sm[];
    float* sW = sm;           // [128][128] (GEMM1: Wi, then W1x)
    float* sX = sm + 16384;   // [64][132]

    const int path = blockIdx.y;
    const int r0   = blockIdx.x * 64;
    const float* X   = path ? liquid : price;
    const float* Wi  = path ? W_v : W_p;
    const float* bi  = path ? b_v : b_p;
    const float* W1x = path ? (W1 + 128 * 128) : W1;

    const int tid = threadIdx.x;
    const int rg = tid >> 4;        // 16 groups x 4 rows
    const int kg = tid & 15;
    const int k0 = kg * 8;

    for (int i = tid; i < 4096; i += 256) ((float4*)sW)[i] = ((const float4*)Wi)[i];
    for (int i = tid; i < 2048; i += 256) {
        int r = i >> 5, c = (i & 31) * 4;
        *(float4*)(sX + r * 132 + c) = *(const float4*)(X + (size_t)(r0 + r) * 128 + c);
    }
    __syncthreads();

    // ---- GEMM1: Y = X @ Wi + bi ----
    ull acc[4][4];
    {
        float4 blo = *(const float4*)(bi + k0);
        float4 bhi = *(const float4*)(bi + k0 + 4);
        ull i0 = pack2(blo.x, blo.y), i1 = pack2(blo.z, blo.w);
        ull i2 = pack2(bhi.x, bhi.y), i3 = pack2(bhi.z, bhi.w);
#pragma unroll
        for (int rl = 0; rl < 4; rl++) { acc[rl][0]=i0; acc[rl][1]=i1; acc[rl][2]=i2; acc[rl][3]=i3; }
    }
#pragma unroll 4
    for (int d = 0; d < 128; d++) {
        ulonglong2 wa = *(const ulonglong2*)(sW + d * 128 + k0);
        ulonglong2 wb = *(const ulonglong2*)(sW + d * 128 + k0 + 4);
        ull w2[4] = {wa.x, wa.y, wb.x, wb.y};
#pragma unroll
        for (int rl = 0; rl < 4; rl++) {
            float xv = sX[(rg * 4 + rl) * 132 + d];
            ull x2 = pack2(xv, xv);
#pragma unroll
            for (int kk = 0; kk < 4; kk++)
                acc[rl][kk] = fma2(x2, w2[kk], acc[rl][kk]);
        }
    }
    __syncthreads();

    // write Y into sX + global; restage sW = W1x
#pragma unroll
    for (int rl = 0; rl < 4; rl++) {
        float y[8];
#pragma unroll
        for (int kk = 0; kk < 4; kk++) unpack2(acc[rl][kk], y[2*kk], y[2*kk+1]);
        int r = rg * 4 + rl;
        *(float4*)(sX + r * 132 + k0)     = make_float4(y[0], y[1], y[2], y[3]);
        *(float4*)(sX + r * 132 + k0 + 4) = make_float4(y[4], y[5], y[6], y[7]);
        int row = r0 + r;
        if (path == 0) {
            *(float4*)(g_p + (size_t)row * 128 + k0)     = make_float4(y[0], y[1], y[2], y[3]);
            *(float4*)(g_p + (size_t)row * 128 + k0 + 4) = make_float4(y[4], y[5], y[6], y[7]);
        } else {
            int bt = row >> 5, m = row & 31;
            float* dst = g_vT + bt * 4096 + m;
#pragma unroll
            for (int kl = 0; kl < 8; kl++) dst[(k0 + kl) * 32] = y[kl];
        }
    }
    for (int i = tid; i < 4096; i += 256) ((float4*)sW)[i] = ((const float4*)W1x)[i];
    __syncthreads();

    // ---- GEMM2: Z = Y @ W1x (+ b1 on liquid path) ----
    if (path == 0) {
#pragma unroll
        for (int rl = 0; rl < 4; rl++)
#pragma unroll
            for (int kk = 0; kk < 4; kk++) acc[rl][kk] = 0ULL;
    } else {
        float4 blo = *(const float4*)(b1 + k0);
        float4 bhi = *(const float4*)(b1 + k0 + 4);
        ull i0 = pack2(blo.x, blo.y), i1 = pack2(blo.z, blo.w);
        ull i2 = pack2(bhi.x, bhi.y), i3 = pack2(bhi.z, bhi.w);
#pragma unroll
        for (int rl = 0; rl < 4; rl++) { acc[rl][0]=i0; acc[rl][1]=i1; acc[rl][2]=i2; acc[rl][3]=i3; }
    }
#pragma unroll 4
    for (int d = 0; d < 128; d++) {
        ulonglong2 wa = *(const ulonglong2*)(sW + d * 128 + k0);
        ulonglong2 wb = *(const ulonglong2*)(sW + d * 128 + k0 + 4);
        ull w2[4] = {wa.x, wa.y, wb.x, wb.y};
#pragma unroll
        for (int rl = 0; rl < 4; rl++) {
            float xv = sX[(rg * 4 + rl) * 132 + d];
            ull x2 = pack2(xv, xv);
#pragma unroll
            for (int kk = 0; kk < 4; kk++)
                acc[rl][kk] = fma2(x2, w2[kk], acc[rl][kk]);
        }
    }
#pragma unroll
    for (int rl = 0; rl < 4; rl++) {
        float y[8];
#pragma unroll
        for (int kk = 0; kk < 4; kk++) unpack2(acc[rl][kk], y[2*kk], y[2*kk+1]);
        int row = r0 + rg * 4 + rl;
        if (path == 0) {
            *(float4*)(g_A + (size_t)row * 128 + k0)     = make_float4(y[0], y[1], y[2], y[3]);
            *(float4*)(g_A + (size_t)row * 128 + k0 + 4) = make_float4(y[4], y[5], y[6], y[7]);
        } else {
            int bt = row >> 5, m = row & 31;
            float* dst = g_BvT + bt * 4096 + m;
#pragma unroll
            for (int kl = 0; kl < 8; kl++) dst[(k0 + kl) * 32] = y[kl];
        }
    }
}

// ---------------------------------------------------------------------------
// Kernel 2: weight prep into paired-uint2 b-fragment images. grid 6 x 128.
// ---------------------------------------------------------------------------
__global__ void __launch_bounds__(128) k_wprep(const float* __restrict__ W1,
                                               const float* __restrict__ W2)
{
    const int im = blockIdx.x;            // 0..5
    const int mat = im >> 1, lo = im & 1;
    const float* src = (mat == 0) ? (W1 + 256 * 128) : (mat == 1) ? (W1 + 384 * 128) : W2;
    const int n = threadIdx.x;
    for (int s = 0; s < 8; s++)
        for (int j = 0; j < 4; j++) {
            int ka = 16 * s + 2 * j, kb = ka + 8;
            u32 ah, al, bh, bl;
            split2(src[ka * 128 + n], src[(ka + 1) * 128 + n], ah, al);
            split2(src[kb * 128 + n], src[(kb + 1) * 128 + n], bh, bl);
            g_img[im * IMG_N + n * IMG_S2 + 4 * s + j] =
                lo ? make_uint2(al, bl) : make_uint2(ah, bh);
        }
}

// ---------------------------------------------------------------------------
// Kernel 3: persistent HMMA pair kernel, sync-free per unit. grid 148 x 256.
// Warp w: rows ln=w>>1 (m in [(w&1)*16, +16)), all 128 cols.
// smem: 5 resident images (Wc_h,Wc_l,Wd_h,Wd_l,W2_h) + vT + Bv + b2.
// W2_l streamed from gmem (L1-cached) in layer 2.
// ---------------------------------------------------------------------------
__global__ void __launch_bounds__(256, 1) k_pair_mma(const float* __restrict__ b2,
                                                     float* __restrict__ out)
{
    extern __shared__ __align__(16) char smem[];
    uint2* sImg = (uint2*)smem;                     // 5 * 36864 B
    float* sVT  = (float*)(smem + 5 * IMG_N * 8);   // [128][36] v[d][m]
    float* sBv  = sVT + 128 * 36;                   // [128][36] Bv[k][m]
    float* sB2  = sBv + 128 * 36;                   // [128]

    const int tid  = threadIdx.x;
    const int w    = tid >> 5;
    const int lane = tid & 31;
    const int g    = lane >> 2;
    const int j    = lane & 3;
    const int ln   = w >> 1;
    const int mlo  = (w & 1) * 16 + g;
    const int mhi  = mlo + 8;

    // stage resident weights + b2 once
    for (int i = tid; i < 5 * IMG_N; i += 256) sImg[i] = g_img[i];
    for (int i = tid; i < 128; i += 256) sB2[i] = b2[i];

    const int lo_u = (blockIdx.x * 2048) / 148;
    const int hi_u = ((blockIdx.x + 1) * 2048) / 148;
    int cur_bt = -1;

    for (int u = lo_u; u < hi_u; u++) {
        const int bt = u >> 3, tile = u & 7;
        if (bt != cur_bt) {
            __syncthreads();
            const float4* vsrc = (const float4*)(g_vT  + (size_t)bt * 4096);
            const float4* bsrc = (const float4*)(g_BvT + (size_t)bt * 4096);
            for (int i = tid; i < 1024; i += 256) {
                int d = i >> 3, mg = (i & 7) * 4;
                *(float4*)(sVT + d * 36 + mg) = vsrc[i];
                *(float4*)(sBv + d * 36 + mg) = bsrc[i];
            }
            __syncthreads();
            cur_bt = bt;
        }
        const float* prow = g_p + (size_t)(bt * 32 + tile * 4 + ln) * 128;
        const float* arow = g_A + (size_t)(bt * 32 + tile * 4 + ln) * 128;

        // ---- layer 1: acc = (p*v)@Wc + |p-v|@Wd, 3-pass split ----
        float acc[16][4];
#pragma unroll
        for (int nt = 0; nt < 16; nt++)
#pragma unroll
            for (int q = 0; q < 4; q++) acc[nt][q] = 0.0f;

#pragma unroll
        for (int s = 0; s < 8; s++) {
            const int d0 = 16 * s + 2 * j;
            float2 pa = *(const float2*)(prow + d0);
            float2 pb = *(const float2*)(prow + d0 + 8);
            float v0l = sVT[d0 * 36 + mlo],       v1l = sVT[(d0 + 1) * 36 + mlo];
            float v0h = sVT[d0 * 36 + mhi],       v1h = sVT[(d0 + 1) * 36 + mhi];
            float v8l = sVT[(d0 + 8) * 36 + mlo], v9l = sVT[(d0 + 9) * 36 + mlo];
            float v8h = sVT[(d0 + 8) * 36 + mhi], v9h = sVT[(d0 + 9) * 36 + mhi];
            u32 Ph[4], Pl[4], Qh[4], Ql[4];
            split2(pa.x * v0l, pa.y * v1l, Ph[0], Pl[0]);
            split2(pa.x * v0h, pa.y * v1h, Ph[1], Pl[1]);
            split2(pb.x * v8l, pb.y * v9l, Ph[2], Pl[2]);
            split2(pb.x * v8h, pb.y * v9h, Ph[3], Pl[3]);
            split2(fabsf(pa.x - v0l), fabsf(pa.y - v1l), Qh[0], Ql[0]);
            split2(fabsf(pa.x - v0h), fabsf(pa.y - v1h), Qh[1], Ql[1]);
            split2(fabsf(pb.x - v8l), fabsf(pb.y - v9l), Qh[2], Ql[2]);
            split2(fabsf(pb.x - v8h), fabsf(pb.y - v9h), Qh[3], Ql[3]);
#pragma unroll
            for (int nt = 0; nt < 16; nt++) {
                int bi = (8 * nt + g) * IMG_S2 + 4 * s + j;
                uint2 ch = sImg[bi];
                uint2 cl = sImg[IMG_N + bi];
                uint2 dh = sImg[2 * IMG_N + bi];
                uint2 dl = sImg[3 * IMG_N + bi];
                hmma(acc[nt], Ph, ch.x, ch.y);
                hmma(acc[nt], Pl, ch.x, ch.y);
                hmma(acc[nt], Ph, cl.x, cl.y);
                hmma(acc[nt], Qh, dh.x, dh.y);
                hmma(acc[nt], Ql, dh.x, dh.y);
                hmma(acc[nt], Qh, dl.x, dl.y);
            }
        }

        // ---- epilogue 1: z = acc + A + Bv ; H = silu(z) as reg A-frags ----
        u32 Hh[8][4], Hl[8][4];
#pragma unroll
        for (int nt = 0; nt < 16; nt++) {
            int col = 8 * nt + 2 * j;
            float2 a2 = *(const float2*)(arow + col);
            float z0 = acc[nt][0] + a2.x + sBv[col * 36 + mlo];
            float z1 = acc[nt][1] + a2.y + sBv[(col + 1) * 36 + mlo];
            float z2 = acc[nt][2] + a2.x + sBv[col * 36 + mhi];
            float z3 = acc[nt][3] + a2.y + sBv[(col + 1) * 36 + mhi];
            int s2 = nt >> 1, o = (nt & 1) * 2;
            split2(silu_f(z0), silu_f(z1), Hh[s2][o],     Hl[s2][o]);
            split2(silu_f(z2), silu_f(z3), Hh[s2][o + 1], Hl[s2][o + 1]);
        }

        // ---- layer 2: out = H @ W2, 3-pass split (W2_l streamed) ----
        float ac2[16][4];
#pragma unroll
        for (int nt = 0; nt < 16; nt++)
#pragma unroll
            for (int q = 0; q < 4; q++) ac2[nt][q] = 0.0f;

#pragma unroll
        for (int s = 0; s < 8; s++) {
#pragma unroll
            for (int nt = 0; nt < 16; nt++) {
                int bi = (8 * nt + g) * IMG_S2 + 4 * s + j;
                uint2 wh = sImg[4 * IMG_N + bi];
                uint2 wl = __ldg(&g_img[5 * IMG_N + bi]);
                hmma(ac2[nt], Hh[s], wh.x, wh.y);
                hmma(ac2[nt], Hl[s], wh.x, wh.y);
                hmma(ac2[nt], Hh[s], wl.x, wl.y);
            }
        }

        // ---- epilogue 2: + b2, store ----
        float* ob = out + ((size_t)u * 128 + ln * 32) * 128;
#pragma unroll
        for (int nt = 0; nt < 16; nt++) {
            int col = 8 * nt + 2 * j;
            float bb0 = sB2[col], bb1 = sB2[col + 1];
            *(float2*)(ob + (size_t)mlo * 128 + col) =
                make_float2(ac2[nt][0] + bb0, ac2[nt][1] + bb1);
            *(float2*)(ob + (size_t)mhi * 128 + col) =
                make_float2(ac2[nt][2] + bb0, ac2[nt][3] + bb1);
        }
    }
}

// ---------------------------------------------------------------------------
extern "C" void kernel_launch(void* const* d_in, const int* in_sizes, int n_in,
                              void* d_out, int out_size)
{
    const float* price  = (const float*)d_in[0];
    const float* liquid = (const float*)d_in[1];
    const float* W_p = (const float*)d_in[2];
    const float* b_p = (const float*)d_in[3];
    const float* W_v = (const float*)d_in[4];
    const float* b_v = (const float*)d_in[5];
    const float* W1  = (const float*)d_in[6];
    const float* b1  = (const float*)d_in[7];
    const float* W2  = (const float*)d_in[8];
    const float* b2  = (const float*)d_in[9];
    float* out = (float*)d_out;

    const size_t sm1 = (size_t)(16384 + 64 * 132) * sizeof(float);            // 99,328
    const size_t sm2 = 5 * IMG_N * 8 + 2 * 128 * 36 * 4 + 512;                // 221,696
    cudaFuncSetAttribute(k_pre,      cudaFuncAttributeMaxDynamicSharedMemorySize, (int)sm1);
    cudaFuncSetAttribute(k_pair_mma, cudaFuncAttributeMaxDynamicSharedMemorySize, (int)sm2);

    k_pre<<<dim3(128, 2), 256, sm1>>>(price, liquid, W_p, b_p, W_v, b_v, W1, b1);
    k_wprep<<<6, 128>>>(W1, W2);
    k_pair_mma<<<148, 256, sm2>>>(b2, out);
}

// round 6
// speedup vs baseline: 3.0027x; 1.1320x over previous
#include <cuda_runtime.h>
#include <cuda_bf16.h>
#include <cstdint>

// ---------------------------------------------------------------------------
// PairInteractionGrid (sm_103a) R6 — all-HMMA, warp-independent band streams.
//   p  = price @ W_p + b_p ; v = liquid @ W_v + b_v          (k_pre, HMMA 3x)
//   A  = p @ W1p ; Bv = v @ W1v + b1                          (k_pre, HMMA 3x)
//   z(n,m) = A_n + Bv_m + (p*v)@Wc + |p-v|@Wd                 (k_pair, HMMA 3x)
//   out = silu(z) @ W2 + b2                                   (k_pair, HMMA 3x)
// ---------------------------------------------------------------------------

typedef unsigned long long ull;
typedef unsigned int u32;
#define DI __device__ __forceinline__

DI float silu_f(float x) { return __fdividef(x, 1.0f + __expf(-x)); }
DI u32 cvt2(float f0, float f1) {   // f0 -> low half bf16x2
    u32 r; asm("cvt.rn.bf16x2.f32 %0, %1, %2;" : "=r"(r) : "f"(f1), "f"(f0)); return r;
}
DI void split2(float f0, float f1, u32& h, u32& l) {
    h = cvt2(f0, f1);
    float h0 = __uint_as_float(h << 16);
    float h1 = __uint_as_float(h & 0xFFFF0000u);
    l = cvt2(f0 - h0, f1 - h1);
}
DI void hmma(float* c, const u32* a, u32 b0, u32 b1) {
    asm("mma.sync.aligned.m16n8k16.row.col.f32.bf16.bf16.f32 "
        "{%0,%1,%2,%3},{%4,%5,%6,%7},{%8,%9},{%0,%1,%2,%3};"
        : "+f"(c[0]), "+f"(c[1]), "+f"(c[2]), "+f"(c[3])
        : "r"(a[0]), "r"(a[1]), "r"(a[2]), "r"(a[3]), "r"(b0), "r"(b1));
}

// ------------------------- global scratch ----------------------------------
// B=4 T=64 N=32 M=32 D=128 ; BT=256 ; units=2048 ; bands=16384 (16 rows each)
__device__ __align__(16) float g_p  [8192 * 128];     // p[row][d]
__device__ __align__(16) float g_A  [8192 * 128];     // A[row][k]
__device__ __align__(16) float g_vT [256 * 128 * 32]; // vT[bt][d][m]
__device__ __align__(16) float g_BvT[256 * 128 * 32]; // BvT[bt][k][m] (b1 folded)
// 6 images: 0 Wc_h, 1 Wc_l, 2 Wd_h, 3 Wd_l, 4 W2_h, 5 W2_l.
// img[im][n][4s+j] = uint2{ bf16x2(W[16s+2j][n],W[16s+2j+1][n]),
//                           bf16x2(W[16s+2j+8][n],W[16s+2j+9][n]) }
#define IMG_S2 36                 // uint2 stride per n (4 pad)
#define IMG_N  (128 * IMG_S2)     // 4608 uint2 per image (36,864 B)
__device__ __align__(16) uint2 g_img[6 * IMG_N];

// ---------------------------------------------------------------------------
// Kernel 1: HMMA precompute of p, v, A, Bv. grid (64, 2) x 256 thr.
// Block = 128 rows of one path. Warp = 16 rows x 128 cols, no inner barriers.
// GEMM1: Y = X @ Wi + bi ; GEMM2: Z = Y @ W1x (+ b1 on liquid path).
// C-frag of GEMM1 re-split in registers as A-frag of GEMM2.
// ---------------------------------------------------------------------------
__global__ void __launch_bounds__(256, 1) k_pre_mma(
    const float* __restrict__ price, const float* __restrict__ liquid,
    const float* __restrict__ W_p, const float* __restrict__ b_p,
    const float* __restrict__ W_v, const float* __restrict__ b_v,
    const float* __restrict__ W1,  const float* __restrict__ b1)
{
    extern __shared__ __align__(16) char smem[];
    uint2* sWh  = (uint2*)smem;                   // GEMM1 weights hi
    uint2* sWl  = sWh + IMG_N;                    // GEMM1 weights lo
    uint2* sW1h = sWl + IMG_N;                    // GEMM2 weights hi
    uint2* sW1l = sW1h + IMG_N;                   // GEMM2 weights lo
    float* sBi  = (float*)(sW1l + IMG_N);         // [128] GEMM1 bias
    float* sB1  = sBi + 128;                      // [128] GEMM2 bias (path1)

    const int path = blockIdx.y;
    const int r0   = blockIdx.x * 128;
    const float* X   = path ? liquid : price;
    const float* Wi  = path ? W_v : W_p;
    const float* bi  = path ? b_v : b_p;
    const float* W1x = path ? (W1 + 128 * 128) : W1;

    const int tid  = threadIdx.x;
    const int w    = tid >> 5;
    const int lane = tid & 31;
    const int g    = lane >> 2;
    const int j    = lane & 3;

    // ---- build weight images (both GEMMs, hi+lo) ----
    for (int pos = tid; pos < 8192; pos += 256) {
        const int mat = pos >> 12;           // 0: Wi, 1: W1x
        const int idx = pos & 4095;
        const int n  = idx & 127;
        const int sj = idx >> 7;             // 4s + j
        const int s  = sj >> 2, jj = sj & 3;
        const int ka = 16 * s + 2 * jj;
        const float* src = mat ? W1x : Wi;
        u32 h0, l0, h1, l1;
        split2(src[ka * 128 + n],       src[(ka + 1) * 128 + n], h0, l0);
        split2(src[(ka + 8) * 128 + n], src[(ka + 9) * 128 + n], h1, l1);
        uint2* dh = mat ? sW1h : sWh;
        uint2* dl = mat ? sW1l : sWl;
        dh[n * IMG_S2 + sj] = make_uint2(h0, h1);
        dl[n * IMG_S2 + sj] = make_uint2(l0, l1);
    }
    for (int i = tid; i < 128; i += 256) {
        sBi[i] = bi[i];
        sB1[i] = path ? b1[i] : 0.0f;
    }
    __syncthreads();

    // ---- load X A-fragments (split hi/lo) ----
    const int ra = r0 + w * 16 + g;        // this thread's two rows
    const int rb = ra + 8;
    u32 Xh[8][4], Xl[8][4];
#pragma unroll
    for (int s = 0; s < 8; s++) {
        const int ka = 16 * s + 2 * j;
        float2 xa0 = *(const float2*)(X + (size_t)ra * 128 + ka);
        float2 xb0 = *(const float2*)(X + (size_t)rb * 128 + ka);
        float2 xa1 = *(const float2*)(X + (size_t)ra * 128 + ka + 8);
        float2 xb1 = *(const float2*)(X + (size_t)rb * 128 + ka + 8);
        split2(xa0.x, xa0.y, Xh[s][0], Xl[s][0]);
        split2(xb0.x, xb0.y, Xh[s][1], Xl[s][1]);
        split2(xa1.x, xa1.y, Xh[s][2], Xl[s][2]);
        split2(xb1.x, xb1.y, Xh[s][3], Xl[s][3]);
    }

    // ---- GEMM1: Y = X @ Wi (3-pass) ----
    float yacc[16][4];
#pragma unroll
    for (int nt = 0; nt < 16; nt++)
#pragma unroll
        for (int q = 0; q < 4; q++) yacc[nt][q] = 0.0f;
#pragma unroll
    for (int s = 0; s < 8; s++)
#pragma unroll
        for (int nt = 0; nt < 16; nt++) {
            int bi_ = (8 * nt + g) * IMG_S2 + 4 * s + j;
            uint2 wh = sWh[bi_], wl = sWl[bi_];
            hmma(yacc[nt], Xh[s], wh.x, wh.y);
            hmma(yacc[nt], Xl[s], wh.x, wh.y);
            hmma(yacc[nt], Xh[s], wl.x, wl.y);
        }

    // ---- epilogue 1: + bias, store Y, re-split as GEMM2 A-frags ----
    const int bta = ra >> 5, ma = ra & 31;   // transposed-store coords
    const int btb = rb >> 5, mb = rb & 31;
#pragma unroll
    for (int nt = 0; nt < 16; nt++) {
        const int c = 8 * nt + 2 * j;
        float y0 = yacc[nt][0] + sBi[c], y1 = yacc[nt][1] + sBi[c + 1];
        float y2 = yacc[nt][2] + sBi[c], y3 = yacc[nt][3] + sBi[c + 1];
        if (path == 0) {
            *(float2*)(g_p + (size_t)ra * 128 + c) = make_float2(y0, y1);
            *(float2*)(g_p + (size_t)rb * 128 + c) = make_float2(y2, y3);
        } else {
            g_vT[bta * 4096 + c * 32 + ma]       = y0;
            g_vT[bta * 4096 + (c + 1) * 32 + ma] = y1;
            g_vT[btb * 4096 + c * 32 + mb]       = y2;
            g_vT[btb * 4096 + (c + 1) * 32 + mb] = y3;
        }
        const int s2 = nt >> 1, o = (nt & 1) * 2;
        split2(y0, y1, Xh[s2][o],     Xl[s2][o]);      // reuse X frag regs
        split2(y2, y3, Xh[s2][o + 1], Xl[s2][o + 1]);
    }

    // ---- GEMM2: Z = Y @ W1x (3-pass) ----
    float zacc[16][4];
#pragma unroll
    for (int nt = 0; nt < 16; nt++)
#pragma unroll
        for (int q = 0; q < 4; q++) zacc[nt][q] = 0.0f;
#pragma unroll
    for (int s = 0; s < 8; s++)
#pragma unroll
        for (int nt = 0; nt < 16; nt++) {
            int bi_ = (8 * nt + g) * IMG_S2 + 4 * s + j;
            uint2 wh = sW1h[bi_], wl = sW1l[bi_];
            hmma(zacc[nt], Xh[s], wh.x, wh.y);
            hmma(zacc[nt], Xl[s], wh.x, wh.y);
            hmma(zacc[nt], Xh[s], wl.x, wl.y);
        }

    // ---- epilogue 2: + b1 (path1), store Z ----
#pragma unroll
    for (int nt = 0; nt < 16; nt++) {
        const int c = 8 * nt + 2 * j;
        float z0 = zacc[nt][0] + sB1[c], z1 = zacc[nt][1] + sB1[c + 1];
        float z2 = zacc[nt][2] + sB1[c], z3 = zacc[nt][3] + sB1[c + 1];
        if (path == 0) {
            *(float2*)(g_A + (size_t)ra * 128 + c) = make_float2(z0, z1);
            *(float2*)(g_A + (size_t)rb * 128 + c) = make_float2(z2, z3);
        } else {
            g_BvT[bta * 4096 + c * 32 + ma]       = z0;
            g_BvT[bta * 4096 + (c + 1) * 32 + ma] = z1;
            g_BvT[btb * 4096 + c * 32 + mb]       = z2;
            g_BvT[btb * 4096 + (c + 1) * 32 + mb] = z3;
        }
    }
}

// ---------------------------------------------------------------------------
// Kernel 2: weight prep into paired-uint2 b-fragment images. grid 6 x 128.
// ---------------------------------------------------------------------------
__global__ void __launch_bounds__(128) k_wprep(const float* __restrict__ W1,
                                               const float* __restrict__ W2)
{
    const int im = blockIdx.x;            // 0..5
    const int mat = im >> 1, lo = im & 1;
    const float* src = (mat == 0) ? (W1 + 256 * 128) : (mat == 1) ? (W1 + 384 * 128) : W2;
    const int n = threadIdx.x;
    for (int s = 0; s < 8; s++)
        for (int j = 0; j < 4; j++) {
            int ka = 16 * s + 2 * j, kb = ka + 8;
            u32 ah, al, bh, bl;
            split2(src[ka * 128 + n], src[(ka + 1) * 128 + n], ah, al);
            split2(src[kb * 128 + n], src[(kb + 1) * 128 + n], bh, bl);
            g_img[im * IMG_N + n * IMG_S2 + 4 * s + j] =
                lo ? make_uint2(al, bl) : make_uint2(ah, bh);
        }
}

// ---------------------------------------------------------------------------
// Kernel 3: pair kernel — 148 x 384 thr, 12 fully independent warps/CTA.
// Work item = band (16 pair-rows x 128 cols); 16384 bands over 1776 warps.
// smem: 4 resident layer-1 images (Wc_h/l, Wd_h/l) + b2   (148 KB -> L1 ~80KB)
// Streamed via L1: W2_h, W2_l images; vT, BvT, p, A rows.  Zero loop barriers.
// ---------------------------------------------------------------------------
__global__ void __launch_bounds__(384, 1) k_pair_mma(const float* __restrict__ b2,
                                                     float* __restrict__ out)
{
    extern __shared__ __align__(16) char smem[];
    uint2* sImg = (uint2*)smem;                     // 4 * 36,864 B
    float* sB2  = (float*)(smem + 4 * IMG_N * 8);   // [128]

    const int tid  = threadIdx.x;
    const int w    = tid >> 5;
    const int lane = tid & 31;
    const int g    = lane >> 2;
    const int j    = lane & 3;

    for (int i = tid; i < 4 * IMG_N; i += 384) sImg[i] = g_img[i];
    for (int i = tid; i < 128; i += 384) sB2[i] = b2[i];
    __syncthreads();

    const int gw   = blockIdx.x * 12 + w;           // global warp id, 0..1775
    const int b_lo = (int)(((long long)gw * 16384) / 1776);
    const int b_hi = (int)(((long long)(gw + 1) * 16384) / 1776);

    for (int b = b_lo; b < b_hi; b++) {
        const int bt   = b >> 6;
        const int tile = (b >> 3) & 7;
        const int rb   = b & 7;
        const int ln   = rb >> 1;
        const int mlo  = (rb & 1) * 16 + g;
        const int mhi  = mlo + 8;
        const float* prow  = g_p  + (size_t)(bt * 32 + tile * 4 + ln) * 128;
        const float* arow  = g_A  + (size_t)(bt * 32 + tile * 4 + ln) * 128;
        const float* vbase = g_vT  + (size_t)bt * 4096;
        const float* bvb   = g_BvT + (size_t)bt * 4096;

        // ---- layer 1: acc = (p*v)@Wc + |p-v|@Wd, 3-pass split ----
        float acc[16][4];
#pragma unroll
        for (int nt = 0; nt < 16; nt++)
#pragma unroll
            for (int q = 0; q < 4; q++) acc[nt][q] = 0.0f;

#pragma unroll
        for (int s = 0; s < 8; s++) {
            const int d0 = 16 * s + 2 * j;
            float2 pa = *(const float2*)(prow + d0);
            float2 pb = *(const float2*)(prow + d0 + 8);
            float v0l = __ldg(vbase + d0 * 32 + mlo),       v1l = __ldg(vbase + (d0 + 1) * 32 + mlo);
            float v0h = __ldg(vbase + d0 * 32 + mhi),       v1h = __ldg(vbase + (d0 + 1) * 32 + mhi);
            float v8l = __ldg(vbase + (d0 + 8) * 32 + mlo), v9l = __ldg(vbase + (d0 + 9) * 32 + mlo);
            float v8h = __ldg(vbase + (d0 + 8) * 32 + mhi), v9h = __ldg(vbase + (d0 + 9) * 32 + mhi);
            u32 Ph[4], Pl[4], Qh[4], Ql[4];
            split2(pa.x * v0l, pa.y * v1l, Ph[0], Pl[0]);
            split2(pa.x * v0h, pa.y * v1h, Ph[1], Pl[1]);
            split2(pb.x * v8l, pb.y * v9l, Ph[2], Pl[2]);
            split2(pb.x * v8h, pb.y * v9h, Ph[3], Pl[3]);
            split2(fabsf(pa.x - v0l), fabsf(pa.y - v1l), Qh[0], Ql[0]);
            split2(fabsf(pa.x - v0h), fabsf(pa.y - v1h), Qh[1], Ql[1]);
            split2(fabsf(pb.x - v8l), fabsf(pb.y - v9l), Qh[2], Ql[2]);
            split2(fabsf(pb.x - v8h), fabsf(pb.y - v9h), Qh[3], Ql[3]);
#pragma unroll
            for (int nt = 0; nt < 16; nt++) {
                int bi = (8 * nt + g) * IMG_S2 + 4 * s + j;
                uint2 ch = sImg[bi];
                uint2 cl = sImg[IMG_N + bi];
                uint2 dh = sImg[2 * IMG_N + bi];
                uint2 dl = sImg[3 * IMG_N + bi];
                hmma(acc[nt], Ph, ch.x, ch.y);
                hmma(acc[nt], Pl, ch.x, ch.y);
                hmma(acc[nt], Ph, cl.x, cl.y);
                hmma(acc[nt], Qh, dh.x, dh.y);
                hmma(acc[nt], Ql, dh.x, dh.y);
                hmma(acc[nt], Qh, dl.x, dl.y);
            }
        }

        // ---- epilogue 1: z = acc + A + Bv ; H = silu(z) as reg A-frags ----
        u32 Hh[8][4], Hl[8][4];
#pragma unroll
        for (int nt = 0; nt < 16; nt++) {
            int col = 8 * nt + 2 * j;
            float2 a2 = *(const float2*)(arow + col);
            float z0 = acc[nt][0] + a2.x + __ldg(bvb + col * 32 + mlo);
            float z1 = acc[nt][1] + a2.y + __ldg(bvb + (col + 1) * 32 + mlo);
            float z2 = acc[nt][2] + a2.x + __ldg(bvb + col * 32 + mhi);
            float z3 = acc[nt][3] + a2.y + __ldg(bvb + (col + 1) * 32 + mhi);
            int s2 = nt >> 1, o = (nt & 1) * 2;
            split2(silu_f(z0), silu_f(z1), Hh[s2][o],     Hl[s2][o]);
            split2(silu_f(z2), silu_f(z3), Hh[s2][o + 1], Hl[s2][o + 1]);
        }

        // ---- layer 2: out = H @ W2, 3-pass (W2_h/W2_l streamed via L1) ----
        float ac2[16][4];
#pragma unroll
        for (int nt = 0; nt < 16; nt++)
#pragma unroll
            for (int q = 0; q < 4; q++) ac2[nt][q] = 0.0f;

#pragma unroll
        for (int s = 0; s < 8; s++) {
#pragma unroll
            for (int nt = 0; nt < 16; nt++) {
                int bi = (8 * nt + g) * IMG_S2 + 4 * s + j;
                uint2 wh = __ldg(&g_img[4 * IMG_N + bi]);
                uint2 wl = __ldg(&g_img[5 * IMG_N + bi]);
                hmma(ac2[nt], Hh[s], wh.x, wh.y);
                hmma(ac2[nt], Hl[s], wh.x, wh.y);
                hmma(ac2[nt], Hh[s], wl.x, wl.y);
            }
        }

        // ---- epilogue 2: + b2, store ----
        const int u = bt * 8 + tile;
        float* ob = out + ((size_t)u * 128 + ln * 32) * 128;
#pragma unroll
        for (int nt = 0; nt < 16; nt++) {
            int col = 8 * nt + 2 * j;
            float bb0 = sB2[col], bb1 = sB2[col + 1];
            *(float2*)(ob + (size_t)mlo * 128 + col) =
                make_float2(ac2[nt][0] + bb0, ac2[nt][1] + bb1);
            *(float2*)(ob + (size_t)mhi * 128 + col) =
                make_float2(ac2[nt][2] + bb0, ac2[nt][3] + bb1);
        }
    }
}

// ---------------------------------------------------------------------------
extern "C" void kernel_launch(void* const* d_in, const int* in_sizes, int n_in,
                              void* d_out, int out_size)
{
    const float* price  = (const float*)d_in[0];
    const float* liquid = (const float*)d_in[1];
    const float* W_p = (const float*)d_in[2];
    const float* b_p = (const float*)d_in[3];
    const float* W_v = (const float*)d_in[4];
    const float* b_v = (const float*)d_in[5];
    const float* W1  = (const float*)d_in[6];
    const float* b1  = (const float*)d_in[7];
    const float* W2  = (const float*)d_in[8];
    const float* b2  = (const float*)d_in[9];
    float* out = (float*)d_out;

    const size_t sm1 = 4 * IMG_N * 8 + 2 * 128 * 4;   // 148,480
    const size_t sm2 = 4 * IMG_N * 8 + 128 * 4;       // 147,968
    cudaFuncSetAttribute(k_pre_mma,  cudaFuncAttributeMaxDynamicSharedMemorySize, (int)sm1);
    cudaFuncSetAttribute(k_pair_mma, cudaFuncAttributeMaxDynamicSharedMemorySize, (int)sm2);

    k_pre_mma<<<dim3(64, 2), 256, sm1>>>(price, liquid, W_p, b_p, W_v, b_v, W1, b1);
    k_wprep<<<6, 128>>>(W1, W2);
    k_pair_mma<<<148, 384, sm2>>>(b2, out);
}

// round 7
// speedup vs baseline: 3.2884x; 1.0952x over previous
#include <cuda_runtime.h>
#include <cuda_bf16.h>
#include <cstdint>

// ---------------------------------------------------------------------------
// PairInteractionGrid (sm_103a) R7 — HMMA with pass-major 4-way interleaved
// accumulators (RAW-free) + uint4 combo fragment images.
//   p  = price @ W_p + b_p ; v = liquid @ W_v + b_v          (k_pre, HMMA 3x)
//   A  = p @ W1p ; Bv = v @ W1v + b1                          (k_pre, HMMA 3x)
//   z(n,m) = A_n + Bv_m + (p*v)@Wc + |p-v|@Wd                 (k_pair, HMMA 3x)
//   out = silu(z) @ W2 + b2                                   (k_pair, HMMA 3x)
// ---------------------------------------------------------------------------

typedef unsigned int u32;
#define DI __device__ __forceinline__

DI float silu_f(float x) { return __fdividef(x, 1.0f + __expf(-x)); }
DI u32 cvt2(float f0, float f1) {   // f0 -> low half bf16x2
    u32 r; asm("cvt.rn.bf16x2.f32 %0, %1, %2;" : "=r"(r) : "f"(f1), "f"(f0)); return r;
}
DI void split2(float f0, float f1, u32& h, u32& l) {
    h = cvt2(f0, f1);
    float h0 = __uint_as_float(h << 16);
    float h1 = __uint_as_float(h & 0xFFFF0000u);
    l = cvt2(f0 - h0, f1 - h1);
}
DI void hmma(float* c, const u32* a, u32 b0, u32 b1) {
    asm("mma.sync.aligned.m16n8k16.row.col.f32.bf16.bf16.f32 "
        "{%0,%1,%2,%3},{%4,%5,%6,%7},{%8,%9},{%0,%1,%2,%3};"
        : "+f"(c[0]), "+f"(c[1]), "+f"(c[2]), "+f"(c[3])
        : "r"(a[0]), "r"(a[1]), "r"(a[2]), "r"(a[3]), "r"(b0), "r"(b1));
}

// ------------------------- global scratch ----------------------------------
// B=4 T=64 N=32 M=32 D=128 ; BT=256 ; units=2048 ; bands=16384 (16 rows each)
__device__ __align__(16) float g_p  [8192 * 128];     // p[row][d]
__device__ __align__(16) float g_A  [8192 * 128];     // A[row][k]
__device__ __align__(16) float g_vT [256 * 128 * 32]; // vT[bt][d][m]
__device__ __align__(16) float g_BvT[256 * 128 * 32]; // BvT[bt][k][m] (b1 folded)
// combo images: [mat][n][sj] uint4 { hi(k0,k1), hi(k8,k9), lo(k0,k1), lo(k8,k9) }
// mat 0 = Wc, 1 = Wd, 2 = W2 ; sj = 4s + j ; k0 = 16s + 2j
#define IMG4_S 36                   // uint4 stride per n (36 mod 8 == 4 -> conflict-free)
#define IMG4   (128 * IMG4_S)       // 4608 uint4 per image (73,728 B)
__device__ __align__(16) uint4 g_img4[3 * IMG4];

// ---------------------------------------------------------------------------
// Kernel 1: HMMA precompute of p, v, A, Bv. grid (64, 2) x 256 thr.
// Block = 128 rows of one path; warp = 16 rows x 128 cols; pass-major MMAs.
// ---------------------------------------------------------------------------
__global__ void __launch_bounds__(256, 1) k_pre_mma(
    const float* __restrict__ price, const float* __restrict__ liquid,
    const float* __restrict__ W_p, const float* __restrict__ b_p,
    const float* __restrict__ W_v, const float* __restrict__ b_v,
    const float* __restrict__ W1,  const float* __restrict__ b1)
{
    extern __shared__ __align__(16) char smem[];
    uint4* sWc = (uint4*)smem;                    // GEMM1 weight combo image
    uint4* sW1 = sWc + IMG4;                      // GEMM2 weight combo image
    float* sBi = (float*)(sW1 + IMG4);            // [128]
    float* sB1 = sBi + 128;                       // [128]

    const int path = blockIdx.y;
    const int r0   = blockIdx.x * 128;
    const float* X   = path ? liquid : price;
    const float* Wi  = path ? W_v : W_p;
    const float* bi  = path ? b_v : b_p;
    const float* W1x = path ? (W1 + 128 * 128) : W1;

    const int tid  = threadIdx.x;
    const int w    = tid >> 5;
    const int lane = tid & 31;
    const int g    = lane >> 2;
    const int j    = lane & 3;

    // ---- build combo weight images for both GEMMs ----
    for (int pos = tid; pos < 8192; pos += 256) {
        const int mat = pos >> 12;           // 0: Wi, 1: W1x
        const int idx = pos & 4095;
        const int n   = idx & 127;
        const int sj  = idx >> 7;
        const int s   = sj >> 2, jj = sj & 3;
        const int ka  = 16 * s + 2 * jj;
        const float* src = mat ? W1x : Wi;
        u32 ha, la, hb, lb;
        split2(src[ka * 128 + n],       src[(ka + 1) * 128 + n], ha, la);
        split2(src[(ka + 8) * 128 + n], src[(ka + 9) * 128 + n], hb, lb);
        (mat ? sW1 : sWc)[n * IMG4_S + sj] = make_uint4(ha, hb, la, lb);
    }
    for (int i = tid; i < 128; i += 256) {
        sBi[i] = bi[i];
        sB1[i] = path ? b1[i] : 0.0f;
    }
    __syncthreads();

    // ---- load X A-fragments (split hi/lo) ----
    const int ra = r0 + w * 16 + g;
    const int rb = ra + 8;
    u32 Xh[8][4], Xl[8][4];
#pragma unroll
    for (int s = 0; s < 8; s++) {
        const int ka = 16 * s + 2 * j;
        float2 xa0 = *(const float2*)(X + (size_t)ra * 128 + ka);
        float2 xb0 = *(const float2*)(X + (size_t)rb * 128 + ka);
        float2 xa1 = *(const float2*)(X + (size_t)ra * 128 + ka + 8);
        float2 xb1 = *(const float2*)(X + (size_t)rb * 128 + ka + 8);
        split2(xa0.x, xa0.y, Xh[s][0], Xl[s][0]);
        split2(xb0.x, xb0.y, Xh[s][1], Xl[s][1]);
        split2(xa1.x, xa1.y, Xh[s][2], Xl[s][2]);
        split2(xb1.x, xb1.y, Xh[s][3], Xl[s][3]);
    }

    // ---- GEMM1: Y = X @ Wi (3-pass, pass-major 4-way) ----
    float yacc[16][4];
#pragma unroll
    for (int nt = 0; nt < 16; nt++)
#pragma unroll
        for (int q = 0; q < 4; q++) yacc[nt][q] = 0.0f;
#pragma unroll
    for (int s = 0; s < 8; s++)
#pragma unroll
        for (int q = 0; q < 4; q++) {
            uint4 wv[4];
#pragma unroll
            for (int t = 0; t < 4; t++)
                wv[t] = sWc[(8 * (4 * q + t) + g) * IMG4_S + 4 * s + j];
#pragma unroll
            for (int t = 0; t < 4; t++) hmma(yacc[4 * q + t], Xh[s], wv[t].x, wv[t].y);
#pragma unroll
            for (int t = 0; t < 4; t++) hmma(yacc[4 * q + t], Xl[s], wv[t].x, wv[t].y);
#pragma unroll
            for (int t = 0; t < 4; t++) hmma(yacc[4 * q + t], Xh[s], wv[t].z, wv[t].w);
        }

    // ---- epilogue 1: + bias, store Y, re-split as GEMM2 A-frags ----
    const int bta = ra >> 5, ma = ra & 31;
    const int btb = rb >> 5, mb = rb & 31;
#pragma unroll
    for (int nt = 0; nt < 16; nt++) {
        const int c = 8 * nt + 2 * j;
        float y0 = yacc[nt][0] + sBi[c], y1 = yacc[nt][1] + sBi[c + 1];
        float y2 = yacc[nt][2] + sBi[c], y3 = yacc[nt][3] + sBi[c + 1];
        if (path == 0) {
            *(float2*)(g_p + (size_t)ra * 128 + c) = make_float2(y0, y1);
            *(float2*)(g_p + (size_t)rb * 128 + c) = make_float2(y2, y3);
        } else {
            g_vT[bta * 4096 + c * 32 + ma]       = y0;
            g_vT[bta * 4096 + (c + 1) * 32 + ma] = y1;
            g_vT[btb * 4096 + c * 32 + mb]       = y2;
            g_vT[btb * 4096 + (c + 1) * 32 + mb] = y3;
        }
        const int s2 = nt >> 1, o = (nt & 1) * 2;
        split2(y0, y1, Xh[s2][o],     Xl[s2][o]);
        split2(y2, y3, Xh[s2][o + 1], Xl[s2][o + 1]);
    }

    // ---- GEMM2: Z = Y @ W1x (3-pass, pass-major 4-way) ----
    float zacc[16][4];
#pragma unroll
    for (int nt = 0; nt < 16; nt++)
#pragma unroll
        for (int q = 0; q < 4; q++) zacc[nt][q] = 0.0f;
#pragma unroll
    for (int s = 0; s < 8; s++)
#pragma unroll
        for (int q = 0; q < 4; q++) {
            uint4 wv[4];
#pragma unroll
            for (int t = 0; t < 4; t++)
                wv[t] = sW1[(8 * (4 * q + t) + g) * IMG4_S + 4 * s + j];
#pragma unroll
            for (int t = 0; t < 4; t++) hmma(zacc[4 * q + t], Xh[s], wv[t].x, wv[t].y);
#pragma unroll
            for (int t = 0; t < 4; t++) hmma(zacc[4 * q + t], Xl[s], wv[t].x, wv[t].y);
#pragma unroll
            for (int t = 0; t < 4; t++) hmma(zacc[4 * q + t], Xh[s], wv[t].z, wv[t].w);
        }

    // ---- epilogue 2: + b1 (path1), store Z ----
#pragma unroll
    for (int nt = 0; nt < 16; nt++) {
        const int c = 8 * nt + 2 * j;
        float z0 = zacc[nt][0] + sB1[c], z1 = zacc[nt][1] + sB1[c + 1];
        float z2 = zacc[nt][2] + sB1[c], z3 = zacc[nt][3] + sB1[c + 1];
        if (path == 0) {
            *(float2*)(g_A + (size_t)ra * 128 + c) = make_float2(z0, z1);
            *(float2*)(g_A + (size_t)rb * 128 + c) = make_float2(z2, z3);
        } else {
            g_BvT[bta * 4096 + c * 32 + ma]       = z0;
            g_BvT[bta * 4096 + (c + 1) * 32 + ma] = z1;
            g_BvT[btb * 4096 + c * 32 + mb]       = z2;
            g_BvT[btb * 4096 + (c + 1) * 32 + mb] = z3;
        }
    }
}

// ---------------------------------------------------------------------------
// Kernel 2: weight prep into combo images. grid 3 x 128.
// ---------------------------------------------------------------------------
__global__ void __launch_bounds__(128) k_wprep(const float* __restrict__ W1,
                                               const float* __restrict__ W2)
{
    const int mat = blockIdx.x;           // 0 Wc, 1 Wd, 2 W2
    const float* src = (mat == 0) ? (W1 + 256 * 128) : (mat == 1) ? (W1 + 384 * 128) : W2;
    const int n = threadIdx.x;
    for (int sj = 0; sj < 32; sj++) {
        const int s = sj >> 2, j = sj & 3;
        const int ka = 16 * s + 2 * j;
        u32 ha, la, hb, lb;
        split2(src[ka * 128 + n],       src[(ka + 1) * 128 + n], ha, la);
        split2(src[(ka + 8) * 128 + n], src[(ka + 9) * 128 + n], hb, lb);
        g_img4[mat * IMG4 + n * IMG4_S + sj] = make_uint4(ha, hb, la, lb);
    }
}

// ---------------------------------------------------------------------------
// Kernel 3: pair kernel — 148 x 256 thr, 8 independent warps/CTA.
// Band = 16 pair-rows x 128 cols; 16384 bands over 1184 warps, contiguous.
// smem: Wc+Wd combo images (147 KB) + b2 ; W2 combo streamed via L1 __ldg.
// Pass-major 4-way interleave -> no accumulator RAW chains. No loop barriers.
// ---------------------------------------------------------------------------
__global__ void __launch_bounds__(256, 1) k_pair_mma(const float* __restrict__ b2,
                                                     float* __restrict__ out)
{
    extern __shared__ __align__(16) char smem[];
    uint4* sC  = (uint4*)smem;                      // Wc combo
    uint4* sD  = sC + IMG4;                         // Wd combo
    float* sB2 = (float*)(sD + IMG4);               // [128]

    const int tid  = threadIdx.x;
    const int w    = tid >> 5;
    const int lane = tid & 31;
    const int g    = lane >> 2;
    const int j    = lane & 3;

    for (int i = tid; i < 2 * IMG4; i += 256) ((uint4*)sC)[i] = g_img4[i];
    for (int i = tid; i < 128; i += 256) sB2[i] = b2[i];
    __syncthreads();

    const int gw   = blockIdx.x * 8 + w;            // 0..1183
    const int b_lo = (int)(((long long)gw * 16384) / 1184);
    const int b_hi = (int)(((long long)(gw + 1) * 16384) / 1184);

    for (int b = b_lo; b < b_hi; b++) {
        const int bt   = b >> 6;
        const int tile = (b >> 3) & 7;
        const int rb   = b & 7;
        const int ln   = rb >> 1;
        const int mlo  = (rb & 1) * 16 + g;
        const int mhi  = mlo + 8;
        const float* prow  = g_p  + (size_t)(bt * 32 + tile * 4 + ln) * 128;
        const float* arow  = g_A  + (size_t)(bt * 32 + tile * 4 + ln) * 128;
        const float* vbase = g_vT  + (size_t)bt * 4096;
        const float* bvb   = g_BvT + (size_t)bt * 4096;

        // ---- layer 1: acc = (p*v)@Wc + |p-v|@Wd (3-pass, pass-major) ----
        float acc[16][4];
#pragma unroll
        for (int nt = 0; nt < 16; nt++)
#pragma unroll
            for (int q = 0; q < 4; q++) acc[nt][q] = 0.0f;

#pragma unroll
        for (int s = 0; s < 8; s++) {
            const int d0 = 16 * s + 2 * j;
            float2 pa = *(const float2*)(prow + d0);
            float2 pb = *(const float2*)(prow + d0 + 8);
            float v0l = __ldg(vbase + d0 * 32 + mlo),       v1l = __ldg(vbase + (d0 + 1) * 32 + mlo);
            float v0h = __ldg(vbase + d0 * 32 + mhi),       v1h = __ldg(vbase + (d0 + 1) * 32 + mhi);
            float v8l = __ldg(vbase + (d0 + 8) * 32 + mlo), v9l = __ldg(vbase + (d0 + 9) * 32 + mlo);
            float v8h = __ldg(vbase + (d0 + 8) * 32 + mhi), v9h = __ldg(vbase + (d0 + 9) * 32 + mhi);
            u32 Ph[4], Pl[4], Qh[4], Ql[4];
            split2(pa.x * v0l, pa.y * v1l, Ph[0], Pl[0]);
            split2(pa.x * v0h, pa.y * v1h, Ph[1], Pl[1]);
            split2(pb.x * v8l, pb.y * v9l, Ph[2], Pl[2]);
            split2(pb.x * v8h, pb.y * v9h, Ph[3], Pl[3]);
            split2(fabsf(pa.x - v0l), fabsf(pa.y - v1l), Qh[0], Ql[0]);
            split2(fabsf(pa.x - v0h), fabsf(pa.y - v1h), Qh[1], Ql[1]);
            split2(fabsf(pb.x - v8l), fabsf(pb.y - v9l), Qh[2], Ql[2]);
            split2(fabsf(pb.x - v8h), fabsf(pb.y - v9h), Qh[3], Ql[3]);
#pragma unroll
            for (int q = 0; q < 4; q++) {
                uint4 cv[4];
#pragma unroll
                for (int t = 0; t < 4; t++)
                    cv[t] = sC[(8 * (4 * q + t) + g) * IMG4_S + 4 * s + j];
#pragma unroll
                for (int t = 0; t < 4; t++) hmma(acc[4 * q + t], Ph, cv[t].x, cv[t].y);
#pragma unroll
                for (int t = 0; t < 4; t++) hmma(acc[4 * q + t], Pl, cv[t].x, cv[t].y);
#pragma unroll
                for (int t = 0; t < 4; t++) hmma(acc[4 * q + t], Ph, cv[t].z, cv[t].w);
                uint4 dv[4];
#pragma unroll
                for (int t = 0; t < 4; t++)
                    dv[t] = sD[(8 * (4 * q + t) + g) * IMG4_S + 4 * s + j];
#pragma unroll
                for (int t = 0; t < 4; t++) hmma(acc[4 * q + t], Qh, dv[t].x, dv[t].y);
#pragma unroll
                for (int t = 0; t < 4; t++) hmma(acc[4 * q + t], Ql, dv[t].x, dv[t].y);
#pragma unroll
                for (int t = 0; t < 4; t++) hmma(acc[4 * q + t], Qh, dv[t].z, dv[t].w);
            }
        }

        // ---- epilogue 1: z = acc + A + Bv ; H = silu(z) as reg A-frags ----
        u32 Hh[8][4], Hl[8][4];
#pragma unroll
        for (int nt = 0; nt < 16; nt++) {
            int col = 8 * nt + 2 * j;
            float2 a2 = *(const float2*)(arow + col);
            float z0 = acc[nt][0] + a2.x + __ldg(bvb + col * 32 + mlo);
            float z1 = acc[nt][1] + a2.y + __ldg(bvb + (col + 1) * 32 + mlo);
            float z2 = acc[nt][2] + a2.x + __ldg(bvb + col * 32 + mhi);
            float z3 = acc[nt][3] + a2.y + __ldg(bvb + (col + 1) * 32 + mhi);
            int s2 = nt >> 1, o = (nt & 1) * 2;
            split2(silu_f(z0), silu_f(z1), Hh[s2][o],     Hl[s2][o]);
            split2(silu_f(z2), silu_f(z3), Hh[s2][o + 1], Hl[s2][o + 1]);
        }

        // ---- layer 2: out = H @ W2 (3-pass, pass-major; W2 via L1) ----
        float ac2[16][4];
#pragma unroll
        for (int nt = 0; nt < 16; nt++)
#pragma unroll
            for (int q = 0; q < 4; q++) ac2[nt][q] = 0.0f;

#pragma unroll
        for (int s = 0; s < 8; s++)
#pragma unroll
            for (int q = 0; q < 4; q++) {
                uint4 wv[4];
#pragma unroll
                for (int t = 0; t < 4; t++)
                    wv[t] = __ldg(&g_img4[2 * IMG4 + (8 * (4 * q + t) + g) * IMG4_S + 4 * s + j]);
#pragma unroll
                for (int t = 0; t < 4; t++) hmma(ac2[4 * q + t], Hh[s], wv[t].x, wv[t].y);
#pragma unroll
                for (int t = 0; t < 4; t++) hmma(ac2[4 * q + t], Hl[s], wv[t].x, wv[t].y);
#pragma unroll
                for (int t = 0; t < 4; t++) hmma(ac2[4 * q + t], Hh[s], wv[t].z, wv[t].w);
            }

        // ---- epilogue 2: + b2, store ----
        const int u = bt * 8 + tile;
        float* ob = out + ((size_t)u * 128 + ln * 32) * 128;
#pragma unroll
        for (int nt = 0; nt < 16; nt++) {
            int col = 8 * nt + 2 * j;
            float bb0 = sB2[col], bb1 = sB2[col + 1];
            *(float2*)(ob + (size_t)mlo * 128 + col) =
                make_float2(ac2[nt][0] + bb0, ac2[nt][1] + bb1);
            *(float2*)(ob + (size_t)mhi * 128 + col) =
                make_float2(ac2[nt][2] + bb0, ac2[nt][3] + bb1);
        }
    }
}

// ---------------------------------------------------------------------------
extern "C" void kernel_launch(void* const* d_in, const int* in_sizes, int n_in,
                              void* d_out, int out_size)
{
    const float* price  = (const float*)d_in[0];
    const float* liquid = (const float*)d_in[1];
    const float* W_p = (const float*)d_in[2];
    const float* b_p = (const float*)d_in[3];
    const float* W_v = (const float*)d_in[4];
    const float* b_v = (const float*)d_in[5];
    const float* W1  = (const float*)d_in[6];
    const float* b1  = (const float*)d_in[7];
    const float* W2  = (const float*)d_in[8];
    const float* b2  = (const float*)d_in[9];
    float* out = (float*)d_out;

    const size_t sm1 = 2 * IMG4 * 16 + 2 * 128 * 4;   // 148,480
    const size_t sm2 = 2 * IMG4 * 16 + 128 * 4;       // 147,968
    cudaFuncSetAttribute(k_pre_mma,  cudaFuncAttributeMaxDynamicSharedMemorySize, (int)sm1);
    cudaFuncSetAttribute(k_pair_mma, cudaFuncAttributeMaxDynamicSharedMemorySize, (int)sm2);

    k_pre_mma<<<dim3(64, 2), 256, sm1>>>(price, liquid, W_p, b_p, W_v, b_v, W1, b1);
    k_wprep<<<3, 128>>>(W1, W2);
    k_pair_mma<<<148, 256, sm2>>>(b2, out);
}

// round 8
// speedup vs baseline: 3.3702x; 1.0249x over previous
#include <cuda_runtime.h>
#include <cuda_bf16.h>
#include <cstdint>

// ---------------------------------------------------------------------------
// PairInteractionGrid (sm_103a) R8 — HMMA 3-pass split, pass-major interleave.
//   p  = price @ W_p + b_p ; v = liquid @ W_v + b_v          (k_pre, HMMA 3x)
//   A  = p @ W1p ; Bv = v @ W1v + b1                          (k_pre, HMMA 3x)
//   z(n,m) = A_n + Bv_m + (p*v)@Wc + |p-v|@Wd                 (k_pair, HMMA 3x)
//   out = silu(z) @ W2 + b2                                   (k_pair, HMMA 3x)
// R8: k_pre = 2 CTA/SM streaming (no smem/barriers); v/Bv row-major (coalesced
// float2 loads); batched B-fragment LDS.
// ---------------------------------------------------------------------------

typedef unsigned int u32;
#define DI __device__ __forceinline__

DI float silu_f(float x) { return __fdividef(x, 1.0f + __expf(-x)); }
DI u32 cvt2(float f0, float f1) {   // f0 -> low half bf16x2
    u32 r; asm("cvt.rn.bf16x2.f32 %0, %1, %2;" : "=r"(r) : "f"(f1), "f"(f0)); return r;
}
DI void split2(float f0, float f1, u32& h, u32& l) {
    h = cvt2(f0, f1);
    float h0 = __uint_as_float(h << 16);
    float h1 = __uint_as_float(h & 0xFFFF0000u);
    l = cvt2(f0 - h0, f1 - h1);
}
DI void hmma(float* c, const u32* a, u32 b0, u32 b1) {
    asm("mma.sync.aligned.m16n8k16.row.col.f32.bf16.bf16.f32 "
        "{%0,%1,%2,%3},{%4,%5,%6,%7},{%8,%9},{%0,%1,%2,%3};"
        : "+f"(c[0]), "+f"(c[1]), "+f"(c[2]), "+f"(c[3])
        : "r"(a[0]), "r"(a[1]), "r"(a[2]), "r"(a[3]), "r"(b0), "r"(b1));
}

// ------------------------- global scratch ----------------------------------
// B=4 T=64 N=32 M=32 D=128 ; BT=256 ; units=2048 ; bands=16384 (16 rows each)
__device__ __align__(16) float g_p [8192 * 128];   // p[row][d]   row=bt*32+n
__device__ __align__(16) float g_A [8192 * 128];   // A[row][k]
__device__ __align__(16) float g_v [8192 * 128];   // v[row][d]   row=bt*32+m
__device__ __align__(16) float g_Bv[8192 * 128];   // Bv[row][k]  (b1 folded)
// combo images: [mat][n][sj] uint4 { hi(k0,k1), hi(k8,k9), lo(k0,k1), lo(k8,k9) }
// mat: 0 Wc, 1 Wd, 2 W2, 3 W_p, 4 W_v, 5 W1p, 6 W1v ; sj = 4s+j ; k0 = 16s+2j
#define IMG4_S 36                   // uint4 stride per n
#define IMG4   (128 * IMG4_S)       // 4608 uint4 per image (73,728 B)
__device__ __align__(16) uint4 g_img4[7 * IMG4];

// ---------------------------------------------------------------------------
// Kernel 1: weight prep into combo images. grid 7 x 256.
// ---------------------------------------------------------------------------
__global__ void __launch_bounds__(256) k_wprep(const float* __restrict__ W_p,
                                               const float* __restrict__ W_v,
                                               const float* __restrict__ W1,
                                               const float* __restrict__ W2)
{
    const int mat = blockIdx.x;
    const float* src =
        (mat == 0) ? (W1 + 256 * 128) :
        (mat == 1) ? (W1 + 384 * 128) :
        (mat == 2) ? W2 :
        (mat == 3) ? W_p :
        (mat == 4) ? W_v :
        (mat == 5) ? W1 : (W1 + 128 * 128);
    for (int pos = threadIdx.x; pos < 4096; pos += 256) {
        const int n  = pos & 127;
        const int sj = pos >> 7;
        const int s  = sj >> 2, j = sj & 3;
        const int ka = 16 * s + 2 * j;
        u32 ha, la, hb, lb;
        split2(src[ka * 128 + n],       src[(ka + 1) * 128 + n], ha, la);
        split2(src[(ka + 8) * 128 + n], src[(ka + 9) * 128 + n], hb, lb);
        g_img4[mat * IMG4 + n * IMG4_S + sj] = make_uint4(ha, hb, la, lb);
    }
}

// ---------------------------------------------------------------------------
// Kernel 2: HMMA precompute of p, v, A, Bv. grid (128, 2) x 128 thr, 2 CTA/SM.
// Block = 64 rows of one path; warp = 16 rows x 128 cols. All weights via
// __ldg streams (no smem, no barriers).
// ---------------------------------------------------------------------------
__global__ void __launch_bounds__(128, 2) k_pre_mma(
    const float* __restrict__ price, const float* __restrict__ liquid,
    const float* __restrict__ b_p,   const float* __restrict__ b_v,
    const float* __restrict__ b1)
{
    const int path = blockIdx.y;
    const int r0   = blockIdx.x * 64;
    const float* X  = path ? liquid : price;
    const float* bi = path ? b_v : b_p;
    const uint4* imgW  = g_img4 + (3 + path) * IMG4;   // W_p / W_v
    const uint4* imgW1 = g_img4 + (5 + path) * IMG4;   // W1p / W1v
    float* dstY = path ? g_v  : g_p;
    float* dstZ = path ? g_Bv : g_A;

    const int tid  = threadIdx.x;
    const int w    = tid >> 5;
    const int lane = tid & 31;
    const int g    = lane >> 2;
    const int j    = lane & 3;

    // ---- load X A-fragments (split hi/lo) ----
    const int ra = r0 + w * 16 + g;
    const int rb = ra + 8;
    u32 Xh[8][4], Xl[8][4];
#pragma unroll
    for (int s = 0; s < 8; s++) {
        const int ka = 16 * s + 2 * j;
        float2 xa0 = *(const float2*)(X + (size_t)ra * 128 + ka);
        float2 xb0 = *(const float2*)(X + (size_t)rb * 128 + ka);
        float2 xa1 = *(const float2*)(X + (size_t)ra * 128 + ka + 8);
        float2 xb1 = *(const float2*)(X + (size_t)rb * 128 + ka + 8);
        split2(xa0.x, xa0.y, Xh[s][0], Xl[s][0]);
        split2(xb0.x, xb0.y, Xh[s][1], Xl[s][1]);
        split2(xa1.x, xa1.y, Xh[s][2], Xl[s][2]);
        split2(xb1.x, xb1.y, Xh[s][3], Xl[s][3]);
    }

    // ---- GEMM1: Y = X @ Wi (3-pass, pass-major 4-way) ----
    float yacc[16][4];
#pragma unroll
    for (int nt = 0; nt < 16; nt++)
#pragma unroll
        for (int q = 0; q < 4; q++) yacc[nt][q] = 0.0f;
#pragma unroll
    for (int s = 0; s < 8; s++)
#pragma unroll
        for (int q = 0; q < 4; q++) {
            uint4 wv[4];
#pragma unroll
            for (int t = 0; t < 4; t++)
                wv[t] = __ldg(imgW + (8 * (4 * q + t) + g) * IMG4_S + 4 * s + j);
#pragma unroll
            for (int t = 0; t < 4; t++) hmma(yacc[4 * q + t], Xh[s], wv[t].x, wv[t].y);
#pragma unroll
            for (int t = 0; t < 4; t++) hmma(yacc[4 * q + t], Xl[s], wv[t].x, wv[t].y);
#pragma unroll
            for (int t = 0; t < 4; t++) hmma(yacc[4 * q + t], Xh[s], wv[t].z, wv[t].w);
        }

    // ---- epilogue 1: + bias, store Y row-major, re-split as GEMM2 A-frags ----
#pragma unroll
    for (int nt = 0; nt < 16; nt++) {
        const int c = 8 * nt + 2 * j;
        const float bb0 = __ldg(bi + c), bb1 = __ldg(bi + c + 1);
        float y0 = yacc[nt][0] + bb0, y1 = yacc[nt][1] + bb1;
        float y2 = yacc[nt][2] + bb0, y3 = yacc[nt][3] + bb1;
        *(float2*)(dstY + (size_t)ra * 128 + c) = make_float2(y0, y1);
        *(float2*)(dstY + (size_t)rb * 128 + c) = make_float2(y2, y3);
        const int s2 = nt >> 1, o = (nt & 1) * 2;
        split2(y0, y1, Xh[s2][o],     Xl[s2][o]);
        split2(y2, y3, Xh[s2][o + 1], Xl[s2][o + 1]);
    }

    // ---- GEMM2: Z = Y @ W1x (3-pass, pass-major 4-way) ----
    float zacc[16][4];
#pragma unroll
    for (int nt = 0; nt < 16; nt++)
#pragma unroll
        for (int q = 0; q < 4; q++) zacc[nt][q] = 0.0f;
#pragma unroll
    for (int s = 0; s < 8; s++)
#pragma unroll
        for (int q = 0; q < 4; q++) {
            uint4 wv[4];
#pragma unroll
            for (int t = 0; t < 4; t++)
                wv[t] = __ldg(imgW1 + (8 * (4 * q + t) + g) * IMG4_S + 4 * s + j);
#pragma unroll
            for (int t = 0; t < 4; t++) hmma(zacc[4 * q + t], Xh[s], wv[t].x, wv[t].y);
#pragma unroll
            for (int t = 0; t < 4; t++) hmma(zacc[4 * q + t], Xl[s], wv[t].x, wv[t].y);
#pragma unroll
            for (int t = 0; t < 4; t++) hmma(zacc[4 * q + t], Xh[s], wv[t].z, wv[t].w);
        }

    // ---- epilogue 2: (+ b1 on liquid path), store Z row-major ----
#pragma unroll
    for (int nt = 0; nt < 16; nt++) {
        const int c = 8 * nt + 2 * j;
        const float bb0 = path ? __ldg(b1 + c)     : 0.0f;
        const float bb1 = path ? __ldg(b1 + c + 1) : 0.0f;
        *(float2*)(dstZ + (size_t)ra * 128 + c) =
            make_float2(zacc[nt][0] + bb0, zacc[nt][1] + bb1);
        *(float2*)(dstZ + (size_t)rb * 128 + c) =
            make_float2(zacc[nt][2] + bb0, zacc[nt][3] + bb1);
    }
}

// ---------------------------------------------------------------------------
// Kernel 3: pair kernel — 148 x 256 thr, 8 independent warps/CTA.
// Band = 16 pair-rows x 128 cols; 16384 bands over 1184 warps, contiguous.
// smem: Wc+Wd combo images (147 KB) + b2 ; W2 combo + v/Bv/p/A via L1 __ldg.
// Pass-major 4-way interleave; batched B-fragment loads; no loop barriers.
// ---------------------------------------------------------------------------
__global__ void __launch_bounds__(256, 1) k_pair_mma(const float* __restrict__ b2,
                                                     float* __restrict__ out)
{
    extern __shared__ __align__(16) char smem[];
    uint4* sC  = (uint4*)smem;                      // Wc combo
    uint4* sD  = sC + IMG4;                         // Wd combo
    float* sB2 = (float*)(sD + IMG4);               // [128]

    const int tid  = threadIdx.x;
    const int w    = tid >> 5;
    const int lane = tid & 31;
    const int g    = lane >> 2;
    const int j    = lane & 3;

    for (int i = tid; i < 2 * IMG4; i += 256) ((uint4*)sC)[i] = g_img4[i];
    for (int i = tid; i < 128; i += 256) sB2[i] = b2[i];
    __syncthreads();

    const int gw   = blockIdx.x * 8 + w;            // 0..1183
    const int b_lo = (int)(((long long)gw * 16384) / 1184);
    const int b_hi = (int)(((long long)(gw + 1) * 16384) / 1184);

    for (int b = b_lo; b < b_hi; b++) {
        const int bt   = b >> 6;
        const int tile = (b >> 3) & 7;
        const int rb   = b & 7;
        const int ln   = rb >> 1;
        const int mlo  = (rb & 1) * 16 + g;
        const int mhi  = mlo + 8;
        const float* prow = g_p  + (size_t)(bt * 32 + tile * 4 + ln) * 128;
        const float* arow = g_A  + (size_t)(bt * 32 + tile * 4 + ln) * 128;
        const float* vlo  = g_v  + (size_t)(bt * 32 + mlo) * 128;
        const float* vhi  = g_v  + (size_t)(bt * 32 + mhi) * 128;
        const float* bvlo = g_Bv + (size_t)(bt * 32 + mlo) * 128;
        const float* bvhi = g_Bv + (size_t)(bt * 32 + mhi) * 128;

        // ---- layer 1: acc = (p*v)@Wc + |p-v|@Wd (3-pass, pass-major) ----
        float acc[16][4];
#pragma unroll
        for (int nt = 0; nt < 16; nt++)
#pragma unroll
            for (int q = 0; q < 4; q++) acc[nt][q] = 0.0f;

#pragma unroll
        for (int s = 0; s < 8; s++) {
            const int d0 = 16 * s + 2 * j;
            float2 pa  = *(const float2*)(prow + d0);
            float2 pb  = *(const float2*)(prow + d0 + 8);
            float2 va0 = __ldg((const float2*)(vlo + d0));
            float2 vb0 = __ldg((const float2*)(vhi + d0));
            float2 va8 = __ldg((const float2*)(vlo + d0 + 8));
            float2 vb8 = __ldg((const float2*)(vhi + d0 + 8));
            u32 Ph[4], Pl[4], Qh[4], Ql[4];
            split2(pa.x * va0.x, pa.y * va0.y, Ph[0], Pl[0]);
            split2(pa.x * vb0.x, pa.y * vb0.y, Ph[1], Pl[1]);
            split2(pb.x * va8.x, pb.y * va8.y, Ph[2], Pl[2]);
            split2(pb.x * vb8.x, pb.y * vb8.y, Ph[3], Pl[3]);
            split2(fabsf(pa.x - va0.x), fabsf(pa.y - va0.y), Qh[0], Ql[0]);
            split2(fabsf(pa.x - vb0.x), fabsf(pa.y - vb0.y), Qh[1], Ql[1]);
            split2(fabsf(pb.x - va8.x), fabsf(pb.y - va8.y), Qh[2], Ql[2]);
            split2(fabsf(pb.x - vb8.x), fabsf(pb.y - vb8.y), Qh[3], Ql[3]);
#pragma unroll
            for (int q = 0; q < 4; q++) {
                uint4 cv[4], dv[4];
#pragma unroll
                for (int t = 0; t < 4; t++)
                    cv[t] = sC[(8 * (4 * q + t) + g) * IMG4_S + 4 * s + j];
#pragma unroll
                for (int t = 0; t < 4; t++)
                    dv[t] = sD[(8 * (4 * q + t) + g) * IMG4_S + 4 * s + j];
#pragma unroll
                for (int t = 0; t < 4; t++) hmma(acc[4 * q + t], Ph, cv[t].x, cv[t].y);
#pragma unroll
                for (int t = 0; t < 4; t++) hmma(acc[4 * q + t], Pl, cv[t].x, cv[t].y);
#pragma unroll
                for (int t = 0; t < 4; t++) hmma(acc[4 * q + t], Ph, cv[t].z, cv[t].w);
#pragma unroll
                for (int t = 0; t < 4; t++) hmma(acc[4 * q + t], Qh, dv[t].x, dv[t].y);
#pragma unroll
                for (int t = 0; t < 4; t++) hmma(acc[4 * q + t], Ql, dv[t].x, dv[t].y);
#pragma unroll
                for (int t = 0; t < 4; t++) hmma(acc[4 * q + t], Qh, dv[t].z, dv[t].w);
            }
        }

        // ---- epilogue 1: z = acc + A + Bv ; H = silu(z) as reg A-frags ----
        u32 Hh[8][4], Hl[8][4];
#pragma unroll
        for (int nt = 0; nt < 16; nt++) {
            int col = 8 * nt + 2 * j;
            float2 a2 = *(const float2*)(arow + col);
            float2 bl = __ldg((const float2*)(bvlo + col));
            float2 bh = __ldg((const float2*)(bvhi + col));
            float z0 = acc[nt][0] + a2.x + bl.x;
            float z1 = acc[nt][1] + a2.y + bl.y;
            float z2 = acc[nt][2] + a2.x + bh.x;
            float z3 = acc[nt][3] + a2.y + bh.y;
            int s2 = nt >> 1, o = (nt & 1) * 2;
            split2(silu_f(z0), silu_f(z1), Hh[s2][o],     Hl[s2][o]);
            split2(silu_f(z2), silu_f(z3), Hh[s2][o + 1], Hl[s2][o + 1]);
        }

        // ---- layer 2: out = H @ W2 (3-pass, pass-major; W2 via L1) ----
        float ac2[16][4];
#pragma unroll
        for (int nt = 0; nt < 16; nt++)
#pragma unroll
            for (int q = 0; q < 4; q++) ac2[nt][q] = 0.0f;

#pragma unroll
        for (int s = 0; s < 8; s++)
#pragma unroll
            for (int q = 0; q < 4; q++) {
                uint4 wv[4];
#pragma unroll
                for (int t = 0; t < 4; t++)
                    wv[t] = __ldg(&g_img4[2 * IMG4 + (8 * (4 * q + t) + g) * IMG4_S + 4 * s + j]);
#pragma unroll
                for (int t = 0; t < 4; t++) hmma(ac2[4 * q + t], Hh[s], wv[t].x, wv[t].y);
#pragma unroll
                for (int t = 0; t < 4; t++) hmma(ac2[4 * q + t], Hl[s], wv[t].x, wv[t].y);
#pragma unroll
                for (int t = 0; t < 4; t++) hmma(ac2[4 * q + t], Hh[s], wv[t].z, wv[t].w);
            }

        // ---- epilogue 2: + b2, store ----
        const int u = bt * 8 + tile;
        float* ob = out + ((size_t)u * 128 + ln * 32) * 128;
#pragma unroll
        for (int nt = 0; nt < 16; nt++) {
            int col = 8 * nt + 2 * j;
            float bb0 = sB2[col], bb1 = sB2[col + 1];
            *(float2*)(ob + (size_t)mlo * 128 + col) =
                make_float2(ac2[nt][0] + bb0, ac2[nt][1] + bb1);
            *(float2*)(ob + (size_t)mhi * 128 + col) =
                make_float2(ac2[nt][2] + bb0, ac2[nt][3] + bb1);
        }
    }
}

// ---------------------------------------------------------------------------
extern "C" void kernel_launch(void* const* d_in, const int* in_sizes, int n_in,
                              void* d_out, int out_size)
{
    const float* price  = (const float*)d_in[0];
    const float* liquid = (const float*)d_in[1];
    const float* W_p = (const float*)d_in[2];
    const float* b_p = (const float*)d_in[3];
    const float* W_v = (const float*)d_in[4];
    const float* b_v = (const float*)d_in[5];
    const float* W1  = (const float*)d_in[6];
    const float* b1  = (const float*)d_in[7];
    const float* W2  = (const float*)d_in[8];
    const float* b2  = (const float*)d_in[9];
    float* out = (float*)d_out;

    const size_t sm2 = 2 * IMG4 * 16 + 128 * 4;       // 147,968
    cudaFuncSetAttribute(k_pair_mma, cudaFuncAttributeMaxDynamicSharedMemorySize, (int)sm2);

    k_wprep<<<7, 256>>>(W_p, W_v, W1, W2);
    k_pre_mma<<<dim3(128, 2), 128>>>(price, liquid, b_p, b_v, b1);
    k_pair_mma<<<148, 256, sm2>>>(b2, out);
}

// round 9
// speedup vs baseline: 3.5310x; 1.0477x over previous
#include <cuda_runtime.h>
#include <cuda_bf16.h>
#include <cstdint>

// ---------------------------------------------------------------------------
// PairInteractionGrid (sm_103a) R9 — HMMA 3-pass split, depth-8 interleave.
//   p  = price @ W_p + b_p ; v = liquid @ W_v + b_v          (k_pre, HMMA 3x)
//   A  = p @ W1p ; Bv = v @ W1v + b1                          (k_pre, HMMA 3x)
//   z(n,m) = A_n + Bv_m + (p*v)@Wc + |p-v|@Wd                 (k_pair, HMMA 3x)
//   out = silu(z) @ W2 + b2                                   (k_pair, HMMA 3x)
// R9: parallel k_wprep (112 blocks); 8-way accumulator interleave so RAW
// distance (8 x rt) >= HMMA accumulate latency.
// ---------------------------------------------------------------------------

typedef unsigned int u32;
#define DI __device__ __forceinline__

DI float silu_f(float x) { return __fdividef(x, 1.0f + __expf(-x)); }
DI u32 cvt2(float f0, float f1) {   // f0 -> low half bf16x2
    u32 r; asm("cvt.rn.bf16x2.f32 %0, %1, %2;" : "=r"(r) : "f"(f1), "f"(f0)); return r;
}
DI void split2(float f0, float f1, u32& h, u32& l) {
    h = cvt2(f0, f1);
    float h0 = __uint_as_float(h << 16);
    float h1 = __uint_as_float(h & 0xFFFF0000u);
    l = cvt2(f0 - h0, f1 - h1);
}
DI void hmma(float* c, const u32* a, u32 b0, u32 b1) {
    asm("mma.sync.aligned.m16n8k16.row.col.f32.bf16.bf16.f32 "
        "{%0,%1,%2,%3},{%4,%5,%6,%7},{%8,%9},{%0,%1,%2,%3};"
        : "+f"(c[0]), "+f"(c[1]), "+f"(c[2]), "+f"(c[3])
        : "r"(a[0]), "r"(a[1]), "r"(a[2]), "r"(a[3]), "r"(b0), "r"(b1));
}

// ------------------------- global scratch ----------------------------------
// B=4 T=64 N=32 M=32 D=128 ; BT=256 ; units=2048 ; bands=16384 (16 rows each)
__device__ __align__(16) float g_p [8192 * 128];   // p[row][d]   row=bt*32+n
__device__ __align__(16) float g_A [8192 * 128];   // A[row][k]
__device__ __align__(16) float g_v [8192 * 128];   // v[row][d]   row=bt*32+m
__device__ __align__(16) float g_Bv[8192 * 128];   // Bv[row][k]  (b1 folded)
// combo images: [mat][n][sj] uint4 { hi(k0,k1), hi(k8,k9), lo(k0,k1), lo(k8,k9) }
// mat: 0 Wc, 1 Wd, 2 W2, 3 W_p, 4 W_v, 5 W1p, 6 W1v ; sj = 4s+j ; k0 = 16s+2j
#define IMG4_S 36                   // uint4 stride per n
#define IMG4   (128 * IMG4_S)       // 4608 uint4 per image (73,728 B)
__device__ __align__(16) uint4 g_img4[7 * IMG4];

// ---------------------------------------------------------------------------
// Kernel 1: weight prep into combo images. grid (7,16) x 256 (1 elem/thread).
// ---------------------------------------------------------------------------
__global__ void __launch_bounds__(256) k_wprep(const float* __restrict__ W_p,
                                               const float* __restrict__ W_v,
                                               const float* __restrict__ W1,
                                               const float* __restrict__ W2)
{
    const int mat = blockIdx.x;
    const float* src =
        (mat == 0) ? (W1 + 256 * 128) :
        (mat == 1) ? (W1 + 384 * 128) :
        (mat == 2) ? W2 :
        (mat == 3) ? W_p :
        (mat == 4) ? W_v :
        (mat == 5) ? W1 : (W1 + 128 * 128);
    const int pos = blockIdx.y * 256 + threadIdx.x;   // 0..4095
    const int n  = pos & 127;
    const int sj = pos >> 7;
    const int s  = sj >> 2, j = sj & 3;
    const int ka = 16 * s + 2 * j;
    u32 ha, la, hb, lb;
    split2(__ldg(src + ka * 128 + n),       __ldg(src + (ka + 1) * 128 + n), ha, la);
    split2(__ldg(src + (ka + 8) * 128 + n), __ldg(src + (ka + 9) * 128 + n), hb, lb);
    g_img4[mat * IMG4 + n * IMG4_S + sj] = make_uint4(ha, hb, la, lb);
}

// ---------------------------------------------------------------------------
// Kernel 2: HMMA precompute of p, v, A, Bv. grid (128, 2) x 128 thr, 2 CTA/SM.
// Block = 64 rows of one path; warp = 16 rows x 128 cols. All weights via
// __ldg streams (no smem, no barriers). Depth-8 interleave.
// ---------------------------------------------------------------------------
__global__ void __launch_bounds__(128, 2) k_pre_mma(
    const float* __restrict__ price, const float* __restrict__ liquid,
    const float* __restrict__ b_p,   const float* __restrict__ b_v,
    const float* __restrict__ b1)
{
    const int path = blockIdx.y;
    const int r0   = blockIdx.x * 64;
    const float* X  = path ? liquid : price;
    const float* bi = path ? b_v : b_p;
    const uint4* imgW  = g_img4 + (3 + path) * IMG4;   // W_p / W_v
    const uint4* imgW1 = g_img4 + (5 + path) * IMG4;   // W1p / W1v
    float* dstY = path ? g_v  : g_p;
    float* dstZ = path ? g_Bv : g_A;

    const int tid  = threadIdx.x;
    const int w    = tid >> 5;
    const int lane = tid & 31;
    const int g    = lane >> 2;
    const int j    = lane & 3;

    // ---- load X A-fragments (split hi/lo) ----
    const int ra = r0 + w * 16 + g;
    const int rb = ra + 8;
    u32 Xh[8][4], Xl[8][4];
#pragma unroll
    for (int s = 0; s < 8; s++) {
        const int ka = 16 * s + 2 * j;
        float2 xa0 = *(const float2*)(X + (size_t)ra * 128 + ka);
        float2 xb0 = *(const float2*)(X + (size_t)rb * 128 + ka);
        float2 xa1 = *(const float2*)(X + (size_t)ra * 128 + ka + 8);
        float2 xb1 = *(const float2*)(X + (size_t)rb * 128 + ka + 8);
        split2(xa0.x, xa0.y, Xh[s][0], Xl[s][0]);
        split2(xb0.x, xb0.y, Xh[s][1], Xl[s][1]);
        split2(xa1.x, xa1.y, Xh[s][2], Xl[s][2]);
        split2(xb1.x, xb1.y, Xh[s][3], Xl[s][3]);
    }

    // ---- GEMM1: Y = X @ Wi (3-pass, depth-8) ----
    float yacc[16][4];
#pragma unroll
    for (int nt = 0; nt < 16; nt++)
#pragma unroll
        for (int q = 0; q < 4; q++) yacc[nt][q] = 0.0f;
#pragma unroll
    for (int s = 0; s < 8; s++)
#pragma unroll
        for (int q = 0; q < 2; q++) {
            uint4 wv[8];
#pragma unroll
            for (int t = 0; t < 8; t++)
                wv[t] = __ldg(imgW + (8 * (8 * q + t) + g) * IMG4_S + 4 * s + j);
#pragma unroll
            for (int t = 0; t < 8; t++) hmma(yacc[8 * q + t], Xh[s], wv[t].x, wv[t].y);
#pragma unroll
            for (int t = 0; t < 8; t++) hmma(yacc[8 * q + t], Xl[s], wv[t].x, wv[t].y);
#pragma unroll
            for (int t = 0; t < 8; t++) hmma(yacc[8 * q + t], Xh[s], wv[t].z, wv[t].w);
        }

    // ---- epilogue 1: + bias, store Y row-major, re-split as GEMM2 A-frags ----
#pragma unroll
    for (int nt = 0; nt < 16; nt++) {
        const int c = 8 * nt + 2 * j;
        const float bb0 = __ldg(bi + c), bb1 = __ldg(bi + c + 1);
        float y0 = yacc[nt][0] + bb0, y1 = yacc[nt][1] + bb1;
        float y2 = yacc[nt][2] + bb0, y3 = yacc[nt][3] + bb1;
        *(float2*)(dstY + (size_t)ra * 128 + c) = make_float2(y0, y1);
        *(float2*)(dstY + (size_t)rb * 128 + c) = make_float2(y2, y3);
        const int s2 = nt >> 1, o = (nt & 1) * 2;
        split2(y0, y1, Xh[s2][o],     Xl[s2][o]);
        split2(y2, y3, Xh[s2][o + 1], Xl[s2][o + 1]);
    }

    // ---- GEMM2: Z = Y @ W1x (3-pass, depth-8) ----
    float zacc[16][4];
#pragma unroll
    for (int nt = 0; nt < 16; nt++)
#pragma unroll
        for (int q = 0; q < 4; q++) zacc[nt][q] = 0.0f;
#pragma unroll
    for (int s = 0; s < 8; s++)
#pragma unroll
        for (int q = 0; q < 2; q++) {
            uint4 wv[8];
#pragma unroll
            for (int t = 0; t < 8; t++)
                wv[t] = __ldg(imgW1 + (8 * (8 * q + t) + g) * IMG4_S + 4 * s + j);
#pragma unroll
            for (int t = 0; t < 8; t++) hmma(zacc[8 * q + t], Xh[s], wv[t].x, wv[t].y);
#pragma unroll
            for (int t = 0; t < 8; t++) hmma(zacc[8 * q + t], Xl[s], wv[t].x, wv[t].y);
#pragma unroll
            for (int t = 0; t < 8; t++) hmma(zacc[8 * q + t], Xh[s], wv[t].z, wv[t].w);
        }

    // ---- epilogue 2: (+ b1 on liquid path), store Z row-major ----
#pragma unroll
    for (int nt = 0; nt < 16; nt++) {
        const int c = 8 * nt + 2 * j;
        const float bb0 = path ? __ldg(b1 + c)     : 0.0f;
        const float bb1 = path ? __ldg(b1 + c + 1) : 0.0f;
        *(float2*)(dstZ + (size_t)ra * 128 + c) =
            make_float2(zacc[nt][0] + bb0, zacc[nt][1] + bb1);
        *(float2*)(dstZ + (size_t)rb * 128 + c) =
            make_float2(zacc[nt][2] + bb0, zacc[nt][3] + bb1);
    }
}

// ---------------------------------------------------------------------------
// Kernel 3: pair kernel — 148 x 256 thr, 8 independent warps/CTA.
// Band = 16 pair-rows x 128 cols; 16384 bands over 1184 warps, contiguous.
// smem: Wc+Wd combo images (147 KB) + b2 ; W2 combo + v/Bv/p/A via L1 __ldg.
// Depth-8 accumulator interleave; no loop barriers.
// ---------------------------------------------------------------------------
__global__ void __launch_bounds__(256, 1) k_pair_mma(const float* __restrict__ b2,
                                                     float* __restrict__ out)
{
    extern __shared__ __align__(16) char smem[];
    uint4* sC  = (uint4*)smem;                      // Wc combo
    uint4* sD  = sC + IMG4;                         // Wd combo
    float* sB2 = (float*)(sD + IMG4);               // [128]

    const int tid  = threadIdx.x;
    const int w    = tid >> 5;
    const int lane = tid & 31;
    const int g    = lane >> 2;
    const int j    = lane & 3;

    for (int i = tid; i < 2 * IMG4; i += 256) ((uint4*)sC)[i] = g_img4[i];
    for (int i = tid; i < 128; i += 256) sB2[i] = b2[i];
    __syncthreads();

    const int gw   = blockIdx.x * 8 + w;            // 0..1183
    const int b_lo = (int)(((long long)gw * 16384) / 1184);
    const int b_hi = (int)(((long long)(gw + 1) * 16384) / 1184);

    for (int b = b_lo; b < b_hi; b++) {
        const int bt   = b >> 6;
        const int tile = (b >> 3) & 7;
        const int rb   = b & 7;
        const int ln   = rb >> 1;
        const int mlo  = (rb & 1) * 16 + g;
        const int mhi  = mlo + 8;
        const float* prow = g_p  + (size_t)(bt * 32 + tile * 4 + ln) * 128;
        const float* arow = g_A  + (size_t)(bt * 32 + tile * 4 + ln) * 128;
        const float* vlo  = g_v  + (size_t)(bt * 32 + mlo) * 128;
        const float* vhi  = g_v  + (size_t)(bt * 32 + mhi) * 128;
        const float* bvlo = g_Bv + (size_t)(bt * 32 + mlo) * 128;
        const float* bvhi = g_Bv + (size_t)(bt * 32 + mhi) * 128;

        // ---- layer 1: acc = (p*v)@Wc + |p-v|@Wd (3-pass, depth-8) ----
        float acc[16][4];
#pragma unroll
        for (int nt = 0; nt < 16; nt++)
#pragma unroll
            for (int q = 0; q < 4; q++) acc[nt][q] = 0.0f;

#pragma unroll
        for (int s = 0; s < 8; s++) {
            const int d0 = 16 * s + 2 * j;
            float2 pa  = *(const float2*)(prow + d0);
            float2 pb  = *(const float2*)(prow + d0 + 8);
            float2 va0 = __ldg((const float2*)(vlo + d0));
            float2 vb0 = __ldg((const float2*)(vhi + d0));
            float2 va8 = __ldg((const float2*)(vlo + d0 + 8));
            float2 vb8 = __ldg((const float2*)(vhi + d0 + 8));
            u32 Ph[4], Pl[4], Qh[4], Ql[4];
            split2(pa.x * va0.x, pa.y * va0.y, Ph[0], Pl[0]);
            split2(pa.x * vb0.x, pa.y * vb0.y, Ph[1], Pl[1]);
            split2(pb.x * va8.x, pb.y * va8.y, Ph[2], Pl[2]);
            split2(pb.x * vb8.x, pb.y * vb8.y, Ph[3], Pl[3]);
            split2(fabsf(pa.x - va0.x), fabsf(pa.y - va0.y), Qh[0], Ql[0]);
            split2(fabsf(pa.x - vb0.x), fabsf(pa.y - vb0.y), Qh[1], Ql[1]);
            split2(fabsf(pb.x - va8.x), fabsf(pb.y - va8.y), Qh[2], Ql[2]);
            split2(fabsf(pb.x - vb8.x), fabsf(pb.y - vb8.y), Qh[3], Ql[3]);
#pragma unroll
            for (int q = 0; q < 2; q++) {
                uint4 cv[8];
#pragma unroll
                for (int t = 0; t < 8; t++)
                    cv[t] = sC[(8 * (8 * q + t) + g) * IMG4_S + 4 * s + j];
#pragma unroll
                for (int t = 0; t < 8; t++) hmma(acc[8 * q + t], Ph, cv[t].x, cv[t].y);
#pragma unroll
                for (int t = 0; t < 8; t++) hmma(acc[8 * q + t], Pl, cv[t].x, cv[t].y);
#pragma unroll
                for (int t = 0; t < 8; t++) hmma(acc[8 * q + t], Ph, cv[t].z, cv[t].w);
                uint4 dv[8];
#pragma unroll
                for (int t = 0; t < 8; t++)
                    dv[t] = sD[(8 * (8 * q + t) + g) * IMG4_S + 4 * s + j];
#pragma unroll
                for (int t = 0; t < 8; t++) hmma(acc[8 * q + t], Qh, dv[t].x, dv[t].y);
#pragma unroll
                for (int t = 0; t < 8; t++) hmma(acc[8 * q + t], Ql, dv[t].x, dv[t].y);
#pragma unroll
                for (int t = 0; t < 8; t++) hmma(acc[8 * q + t], Qh, dv[t].z, dv[t].w);
            }
        }

        // ---- epilogue 1: z = acc + A + Bv ; H = silu(z) as reg A-frags ----
        u32 Hh[8][4], Hl[8][4];
#pragma unroll
        for (int nt = 0; nt < 16; nt++) {
            int col = 8 * nt + 2 * j;
            float2 a2 = *(const float2*)(arow + col);
            float2 bl = __ldg((const float2*)(bvlo + col));
            float2 bh = __ldg((const float2*)(bvhi + col));
            float z0 = acc[nt][0] + a2.x + bl.x;
            float z1 = acc[nt][1] + a2.y + bl.y;
            float z2 = acc[nt][2] + a2.x + bh.x;
            float z3 = acc[nt][3] + a2.y + bh.y;
            int s2 = nt >> 1, o = (nt & 1) * 2;
            split2(silu_f(z0), silu_f(z1), Hh[s2][o],     Hl[s2][o]);
            split2(silu_f(z2), silu_f(z3), Hh[s2][o + 1], Hl[s2][o + 1]);
        }

        // ---- layer 2: out = H @ W2 (3-pass, depth-8; W2 via L1) ----
        float ac2[16][4];
#pragma unroll
        for (int nt = 0; nt < 16; nt++)
#pragma unroll
            for (int q = 0; q < 4; q++) ac2[nt][q] = 0.0f;

#pragma unroll
        for (int s = 0; s < 8; s++)
#pragma unroll
            for (int q = 0; q < 2; q++) {
                uint4 wv[8];
#pragma unroll
                for (int t = 0; t < 8; t++)
                    wv[t] = __ldg(&g_img4[2 * IMG4 + (8 * (8 * q + t) + g) * IMG4_S + 4 * s + j]);
#pragma unroll
                for (int t = 0; t < 8; t++) hmma(ac2[8 * q + t], Hh[s], wv[t].x, wv[t].y);
#pragma unroll
                for (int t = 0; t < 8; t++) hmma(ac2[8 * q + t], Hl[s], wv[t].x, wv[t].y);
#pragma unroll
                for (int t = 0; t < 8; t++) hmma(ac2[8 * q + t], Hh[s], wv[t].z, wv[t].w);
            }

        // ---- epilogue 2: + b2, store ----
        const int u = bt * 8 + tile;
        float* ob = out + ((size_t)u * 128 + ln * 32) * 128;
#pragma unroll
        for (int nt = 0; nt < 16; nt++) {
            int col = 8 * nt + 2 * j;
            float bb0 = sB2[col], bb1 = sB2[col + 1];
            *(float2*)(ob + (size_t)mlo * 128 + col) =
                make_float2(ac2[nt][0] + bb0, ac2[nt][1] + bb1);
            *(float2*)(ob + (size_t)mhi * 128 + col) =
                make_float2(ac2[nt][2] + bb0, ac2[nt][3] + bb1);
        }
    }
}

// ---------------------------------------------------------------------------
extern "C" void kernel_launch(void* const* d_in, const int* in_sizes, int n_in,
                              void* d_out, int out_size)
{
    const float* price  = (const float*)d_in[0];
    const float* liquid = (const float*)d_in[1];
    const float* W_p = (const float*)d_in[2];
    const float* b_p = (const float*)d_in[3];
    const float* W_v = (const float*)d_in[4];
    const float* b_v = (const float*)d_in[5];
    const float* W1  = (const float*)d_in[6];
    const float* b1  = (const float*)d_in[7];
    const float* W2  = (const float*)d_in[8];
    const float* b2  = (const float*)d_in[9];
    float* out = (float*)d_out;

    const size_t sm2 = 2 * IMG4 * 16 + 128 * 4;       // 147,968
    cudaFuncSetAttribute(k_pair_mma, cudaFuncAttributeMaxDynamicSharedMemorySize, (int)sm2);

    k_wprep<<<dim3(7, 16), 256>>>(W_p, W_v, W1, W2);
    k_pre_mma<<<dim3(128, 2), 128>>>(price, liquid, b_p, b_v, b1);
    k_pair_mma<<<148, 256, sm2>>>(b2, out);
}